// round 1
// baseline (speedup 1.0000x reference)
#include <cuda_runtime.h>
#include <cuda_bf16.h>
#include <math.h>

// ---------------------------------------------------------------------------
// SpGAT: 2-layer GAT.  N=50000 nodes, E=1650000 edges,
// nfeat=256, nhead=8, nhid=64 (F1=512), nclass=40.
// Pipeline:
//   repack W1 -> Wcat[256,512]
//   CSR build (hist/scan/scatter) keyed on edge src
//   GEMM1: H1 = x @ Wcat + b1
//   attn1: s_src1/s_dst1 = per-head dot(H1, a1)
//   agg1 : per-node weighted sum over CSR neighbors -> /rowsum -> elu -> ACC1
//   GEMM2: H2 = ACC1 @ W2 + b2
//   attn2: s_src2/s_dst2
//   agg2 : weighted sum -> /rowsum -> log_softmax -> out
// ---------------------------------------------------------------------------

#define NN     50000
#define NFEAT  256
#define NHID   64
#define NHEAD  8
#define F1     512      // NHEAD*NHID
#define NCLASS 40
#define EMAX   1650000
#define ALPHA  0.2f

// ------------------------- device scratch (static) -------------------------
__device__ float g_H1  [(size_t)NN * F1];
__device__ float g_ACC1[(size_t)NN * F1];
__device__ float g_H2  [(size_t)NN * NCLASS];
__device__ float g_ssrc1[NN * NHEAD];
__device__ float g_sdst1[NN * NHEAD];
__device__ float g_ssrc2[NN];
__device__ float g_sdst2[NN];
__device__ int   g_deg[NN];
__device__ int   g_cnt[NN];
__device__ int   g_rowoff[NN + 1];
__device__ int   g_adj[EMAX];
__device__ float g_Wcat[NFEAT * F1];

// ------------------------------ small kernels ------------------------------
__global__ void repack_W1(const float* __restrict__ W1) {
    int idx = blockIdx.x * blockDim.x + threadIdx.x;
    if (idx < NHEAD * NFEAT * NHID) {
        int h = idx / (NFEAT * NHID);
        int r = idx % (NFEAT * NHID);
        int k = r / NHID, j = r % NHID;
        g_Wcat[k * F1 + h * NHID + j] = W1[idx];
    }
}

__global__ void zero_counts(int n) {
    int i = blockIdx.x * blockDim.x + threadIdx.x;
    if (i < n) { g_deg[i] = 0; g_cnt[i] = 0; }
}

__global__ void hist_kernel(const int* __restrict__ esrc, int E) {
    int e = blockIdx.x * blockDim.x + threadIdx.x;
    if (e < E) atomicAdd(&g_deg[esrc[e]], 1);
}

// single-block inclusive->exclusive scan of g_deg into g_rowoff
__global__ void scan_kernel(int n) {
    __shared__ int buf[1024];
    int tid = threadIdx.x;
    int carry = 0;
    for (int base = 0; base < n; base += 1024) {
        int i = base + tid;
        int v = (i < n) ? g_deg[i] : 0;
        buf[tid] = v;
        __syncthreads();
        #pragma unroll
        for (int off = 1; off < 1024; off <<= 1) {
            int t = (tid >= off) ? buf[tid - off] : 0;
            __syncthreads();
            buf[tid] += t;
            __syncthreads();
        }
        if (i < n) g_rowoff[i] = carry + buf[tid] - v;
        int tot = buf[1023];
        __syncthreads();
        carry += tot;
    }
    if (tid == 0) g_rowoff[n] = carry;
}

__global__ void scatter_kernel(const int* __restrict__ esrc,
                               const int* __restrict__ edst, int E) {
    int e = blockIdx.x * blockDim.x + threadIdx.x;
    if (e < E) {
        int s = esrc[e];
        int pos = g_rowoff[s] + atomicAdd(&g_cnt[s], 1);
        g_adj[pos] = edst[e];
    }
}

// ------------------------------- GEMM 1 ------------------------------------
// H1[M,512] = A[M,256] @ g_Wcat[256,512] + bias[512]
__global__ __launch_bounds__(256) void gemm1_kernel(const float* __restrict__ A,
                                                    const float* __restrict__ bias,
                                                    int M) {
    const int BM = 128, BN = 64, BK = 16;
    __shared__ float As[BK][BM + 1];
    __shared__ float Bs[BK][BN];
    int nblk = F1 / BN;                       // 8
    int bx = blockIdx.x % nblk;
    int by = blockIdx.x / nblk;
    int m0 = by * BM, n0 = bx * BN;
    int tid = threadIdx.x;
    int tr = tid >> 4, tc = tid & 15;         // 16x16 thread grid
    float acc[8][4];
    #pragma unroll
    for (int i = 0; i < 8; i++)
        #pragma unroll
        for (int j = 0; j < 4; j++) acc[i][j] = 0.f;

    for (int k0 = 0; k0 < NFEAT; k0 += BK) {
        #pragma unroll
        for (int it = 0; it < 2; it++) {
            int idx = tid + it * 256;         // 0..511
            int row = idx >> 2, kq = idx & 3;
            float4 v = make_float4(0.f, 0.f, 0.f, 0.f);
            int gr = m0 + row;
            if (gr < M)
                v = *(const float4*)(A + (size_t)gr * NFEAT + k0 + kq * 4);
            As[kq * 4 + 0][row] = v.x;
            As[kq * 4 + 1][row] = v.y;
            As[kq * 4 + 2][row] = v.z;
            As[kq * 4 + 3][row] = v.w;
        }
        {
            int k = tid >> 4, cq = tid & 15;
            float4 v = *(const float4*)(g_Wcat + (size_t)(k0 + k) * F1 + n0 + cq * 4);
            *(float4*)&Bs[k][cq * 4] = v;
        }
        __syncthreads();
        #pragma unroll
        for (int kk = 0; kk < BK; kk++) {
            float4 b4 = *(const float4*)&Bs[kk][tc * 4];
            float b[4] = {b4.x, b4.y, b4.z, b4.w};
            #pragma unroll
            for (int i = 0; i < 8; i++) {
                float a = As[kk][tr * 8 + i];
                #pragma unroll
                for (int j = 0; j < 4; j++) acc[i][j] += a * b[j];
            }
        }
        __syncthreads();
    }
    #pragma unroll
    for (int i = 0; i < 8; i++) {
        int gr = m0 + tr * 8 + i;
        if (gr < M) {
            #pragma unroll
            for (int j = 0; j < 4; j++)
                g_H1[(size_t)gr * F1 + n0 + tc * 4 + j] =
                    acc[i][j] + bias[n0 + tc * 4 + j];
        }
    }
}

// ------------------------------- attn1 -------------------------------------
// one block (256 thr = 8 warps) per node; warp w handles head w
__global__ __launch_bounds__(256) void attn1_kernel(const float* __restrict__ a1) {
    int n = blockIdx.x;
    int w = threadIdx.x >> 5, lane = threadIdx.x & 31;
    const float* hp = g_H1 + (size_t)n * F1 + w * NHID;
    float h0 = hp[lane], h1 = hp[lane + 32];
    const float* av = a1 + w * 2 * NHID;
    float ss = h0 * av[lane] + h1 * av[lane + 32];
    float sd = h0 * av[64 + lane] + h1 * av[96 + lane];
    #pragma unroll
    for (int off = 16; off; off >>= 1) {
        ss += __shfl_down_sync(0xffffffffu, ss, off);
        sd += __shfl_down_sync(0xffffffffu, sd, off);
    }
    if (lane == 0) {
        g_ssrc1[n * NHEAD + w] = ss;
        g_sdst1[n * NHEAD + w] = sd;
    }
}

// ------------------------------- agg1 --------------------------------------
// one block (128 thr) per node; thread t owns features [4t, 4t+4) -> head t/16
#define CH1 16
__global__ __launch_bounds__(128) void agg1_kernel() {
    int n = blockIdx.x;
    int tid = threadIdx.x;
    __shared__ float sw[CH1 * NHEAD];
    __shared__ int   sdst[CH1];
    __shared__ float srs[NHEAD];
    __shared__ float ssh[NHEAD];
    int head = tid >> 4;
    if (tid < NHEAD) { srs[tid] = 0.f; ssh[tid] = g_ssrc1[n * NHEAD + tid]; }
    int start = g_rowoff[n], end = g_rowoff[n + 1];
    float4 acc = make_float4(0.f, 0.f, 0.f, 0.f);
    __syncthreads();

    for (int e0 = start; e0 < end; e0 += CH1) {
        int ne = min(CH1, end - e0);
        if (tid < ne) sdst[tid] = g_adj[e0 + tid];
        __syncthreads();
        if (tid < ne * NHEAD) {
            int i = tid >> 3, h = tid & 7;
            int dst = sdst[i];
            float z = ssh[h] + g_sdst1[dst * NHEAD + h];
            float w = __expf(z > 0.f ? z : ALPHA * z);
            sw[i * NHEAD + h] = w;
            atomicAdd(&srs[h], w);
        }
        __syncthreads();
        for (int i = 0; i < ne; i++) {
            float w = sw[i * NHEAD + head];
            float4 v = *(const float4*)(g_H1 + (size_t)sdst[i] * F1 + tid * 4);
            acc.x += w * v.x; acc.y += w * v.y;
            acc.z += w * v.z; acc.w += w * v.w;
        }
        __syncthreads();
    }
    float inv = 1.0f / srs[head];
    acc.x *= inv; acc.y *= inv; acc.z *= inv; acc.w *= inv;
    // elu
    acc.x = acc.x > 0.f ? acc.x : expm1f(acc.x);
    acc.y = acc.y > 0.f ? acc.y : expm1f(acc.y);
    acc.z = acc.z > 0.f ? acc.z : expm1f(acc.z);
    acc.w = acc.w > 0.f ? acc.w : expm1f(acc.w);
    *(float4*)(g_ACC1 + (size_t)n * F1 + tid * 4) = acc;
}

// ------------------------------- GEMM 2 ------------------------------------
// H2[M,40] = ACC1[M,512] @ W2[512,40] + b2[40]
__global__ __launch_bounds__(256) void gemm2_kernel(const float* __restrict__ W2,
                                                    const float* __restrict__ b2,
                                                    int M) {
    const int BM = 128, BK = 32;
    __shared__ float As[BK][BM + 1];
    __shared__ float Bs[BK][NCLASS];
    int m0 = blockIdx.x * BM;
    int tid = threadIdx.x;
    int tr = tid >> 3;            // 0..31 -> rows 4tr..4tr+3
    int tc = tid & 7;             // 0..7  -> cols 5tc..5tc+4
    float acc[4][5];
    #pragma unroll
    for (int i = 0; i < 4; i++)
        #pragma unroll
        for (int j = 0; j < 5; j++) acc[i][j] = 0.f;

    for (int k0 = 0; k0 < F1; k0 += BK) {
        #pragma unroll
        for (int it = 0; it < 4; it++) {
            int idx = tid + it * 256;       // 0..1023
            int row = idx >> 3, kq = idx & 7;
            float4 v = make_float4(0.f, 0.f, 0.f, 0.f);
            int gr = m0 + row;
            if (gr < M)
                v = *(const float4*)(g_ACC1 + (size_t)gr * F1 + k0 + kq * 4);
            As[kq * 4 + 0][row] = v.x;
            As[kq * 4 + 1][row] = v.y;
            As[kq * 4 + 2][row] = v.z;
            As[kq * 4 + 3][row] = v.w;
        }
        for (int idx = tid; idx < BK * NCLASS; idx += 256) {
            int k = idx / NCLASS, c = idx % NCLASS;
            Bs[k][c] = W2[(size_t)(k0 + k) * NCLASS + c];
        }
        __syncthreads();
        #pragma unroll
        for (int kk = 0; kk < BK; kk++) {
            float b[5];
            #pragma unroll
            for (int j = 0; j < 5; j++) b[j] = Bs[kk][tc * 5 + j];
            #pragma unroll
            for (int i = 0; i < 4; i++) {
                float a = As[kk][tr * 4 + i];
                #pragma unroll
                for (int j = 0; j < 5; j++) acc[i][j] += a * b[j];
            }
        }
        __syncthreads();
    }
    #pragma unroll
    for (int i = 0; i < 4; i++) {
        int gr = m0 + tr * 4 + i;
        if (gr < M) {
            #pragma unroll
            for (int j = 0; j < 5; j++)
                g_H2[(size_t)gr * NCLASS + tc * 5 + j] =
                    acc[i][j] + b2[tc * 5 + j];
        }
    }
}

// ------------------------------- attn2 -------------------------------------
// one warp per node
__global__ __launch_bounds__(256) void attn2_kernel(const float* __restrict__ a2, int Nn) {
    int gw = (blockIdx.x * blockDim.x + threadIdx.x) >> 5;
    int lane = threadIdx.x & 31;
    if (gw >= Nn) return;
    const float* hp = g_H2 + (size_t)gw * NCLASS;
    float v0 = hp[lane];
    float ss = v0 * a2[lane];
    float sd = v0 * a2[NCLASS + lane];
    if (lane < NCLASS - 32) {
        float v1 = hp[lane + 32];
        ss += v1 * a2[lane + 32];
        sd += v1 * a2[NCLASS + lane + 32];
    }
    #pragma unroll
    for (int off = 16; off; off >>= 1) {
        ss += __shfl_down_sync(0xffffffffu, ss, off);
        sd += __shfl_down_sync(0xffffffffu, sd, off);
    }
    if (lane == 0) { g_ssrc2[gw] = ss; g_sdst2[gw] = sd; }
}

// --------------------------- agg2 + log_softmax ----------------------------
#define CH2 32
__global__ __launch_bounds__(64) void agg2_kernel(float* __restrict__ out) {
    int n = blockIdx.x;
    int tid = threadIdx.x;
    __shared__ float sw[CH2];
    __shared__ int   sdst[CH2];
    __shared__ float srs;
    __shared__ float red[64];
    if (tid == 0) srs = 0.f;
    int start = g_rowoff[n], end = g_rowoff[n + 1];
    float ssrc = g_ssrc2[n];
    float acc = 0.f;
    __syncthreads();

    for (int e0 = start; e0 < end; e0 += CH2) {
        int ne = min(CH2, end - e0);
        if (tid < ne) {
            int d = g_adj[e0 + tid];
            sdst[tid] = d;
            float z = ssrc + g_sdst2[d];
            float w = __expf(z > 0.f ? z : ALPHA * z);
            sw[tid] = w;
            atomicAdd(&srs, w);
        }
        __syncthreads();
        if (tid < NCLASS) {
            for (int i = 0; i < ne; i++)
                acc += sw[i] * g_H2[(size_t)sdst[i] * NCLASS + tid];
        }
        __syncthreads();
    }
    float v = acc / srs;
    // log_softmax over 40 values
    red[tid] = (tid < NCLASS) ? v : -1e30f;
    __syncthreads();
    #pragma unroll
    for (int s = 32; s; s >>= 1) {
        if (tid < s) red[tid] = fmaxf(red[tid], red[tid + s]);
        __syncthreads();
    }
    float mx = red[0];
    __syncthreads();
    red[tid] = (tid < NCLASS) ? __expf(v - mx) : 0.f;
    __syncthreads();
    #pragma unroll
    for (int s = 32; s; s >>= 1) {
        if (tid < s) red[tid] += red[tid + s];
        __syncthreads();
    }
    float lse = logf(red[0]) + mx;
    if (tid < NCLASS) out[(size_t)n * NCLASS + tid] = v - lse;
}

// ------------------------------- launcher ----------------------------------
extern "C" void kernel_launch(void* const* d_in, const int* in_sizes, int n_in,
                              void* d_out, int out_size) {
    const float* x  = (const float*)d_in[0];
    const int*   ed = (const int*)  d_in[1];
    const float* W1 = (const float*)d_in[2];
    const float* b1 = (const float*)d_in[3];
    const float* a1 = (const float*)d_in[4];
    const float* W2 = (const float*)d_in[5];
    const float* b2 = (const float*)d_in[6];
    const float* a2 = (const float*)d_in[7];
    float* out = (float*)d_out;

    int N = in_sizes[0] / NFEAT;
    int E = in_sizes[1] / 2;
    const int* esrc = ed;
    const int* edst = ed + E;

    repack_W1<<<(NHEAD * NFEAT * NHID + 255) / 256, 256>>>(W1);
    zero_counts<<<(N + 255) / 256, 256>>>(N);
    hist_kernel<<<(E + 255) / 256, 256>>>(esrc, E);
    scan_kernel<<<1, 1024>>>(N);
    scatter_kernel<<<(E + 255) / 256, 256>>>(esrc, edst, E);

    gemm1_kernel<<<((N + 127) / 128) * (F1 / 64), 256>>>(x, b1, N);
    attn1_kernel<<<N, 256>>>(a1);
    agg1_kernel<<<N, 128>>>();

    gemm2_kernel<<<(N + 127) / 128, 256>>>(W2, b2, N);
    attn2_kernel<<<(N * 32 + 255) / 256, 256>>>(a2, N);
    agg2_kernel<<<N, 64>>>(out);
}

// round 2
// speedup vs baseline: 1.1684x; 1.1684x over previous
#include <cuda_runtime.h>
#include <cuda_bf16.h>
#include <math.h>

// ---------------------------------------------------------------------------
// SpGAT: 2-layer GAT.  N=50000, E=1650000, nfeat=256, nhead=8, nhid=64
// (F1=512), nclass=40.
// R1 changes vs R0:
//   * hierarchical 3-kernel scan (was 81us single-block ladder)
//   * GEMM1: 128x128 block tile, 8x8 per-thread register tile
//   * GEMM1 epilogue also emits bf16 H1; agg1 gathers bf16 (halves L2 traffic)
// ---------------------------------------------------------------------------

#define NN     50000
#define NFEAT  256
#define NHID   64
#define NHEAD  8
#define F1     512
#define NCLASS 40
#define EMAX   1650000
#define ALPHA  0.2f

// ------------------------- device scratch (static) -------------------------
__device__ float g_H1  [(size_t)NN * F1];
__device__ __nv_bfloat16 g_H1b[(size_t)NN * F1];
__device__ float g_ACC1[(size_t)NN * F1];
__device__ float g_H2  [(size_t)NN * NCLASS];
__device__ float g_ssrc1[NN * NHEAD];
__device__ float g_sdst1[NN * NHEAD];
__device__ float g_ssrc2[NN];
__device__ float g_sdst2[NN];
__device__ int   g_deg[NN];
__device__ int   g_cnt[NN];
__device__ int   g_rowoff[NN + 1];
__device__ int   g_adj[EMAX];
__device__ float g_Wcat[NFEAT * F1];
__device__ int   g_bsum[64];
__device__ int   g_boff[64];

// ------------------------------ small kernels ------------------------------
__global__ void repack_W1(const float* __restrict__ W1) {
    int idx = blockIdx.x * blockDim.x + threadIdx.x;
    if (idx < NHEAD * NFEAT * NHID) {
        int h = idx / (NFEAT * NHID);
        int r = idx % (NFEAT * NHID);
        int k = r / NHID, j = r % NHID;
        g_Wcat[k * F1 + h * NHID + j] = W1[idx];
    }
}

__global__ void zero_counts(int n) {
    int i = blockIdx.x * blockDim.x + threadIdx.x;
    if (i < n) { g_deg[i] = 0; g_cnt[i] = 0; }
}

__global__ void hist_kernel(const int* __restrict__ esrc, int E) {
    int e = blockIdx.x * blockDim.x + threadIdx.x;
    if (e < E) atomicAdd(&g_deg[esrc[e]], 1);
}

// ---- hierarchical scan: block scan -> sum scan -> add offsets ----
__global__ __launch_bounds__(1024) void scan_block_kernel(int n) {
    int tid = threadIdx.x;
    int gid = blockIdx.x * 1024 + tid;
    int lane = tid & 31, wid = tid >> 5;
    int v = (gid < n) ? g_deg[gid] : 0;
    int x = v;
    #pragma unroll
    for (int off = 1; off < 32; off <<= 1) {
        int t = __shfl_up_sync(0xffffffffu, x, off);
        if (lane >= off) x += t;
    }
    __shared__ int wsum[32];
    if (lane == 31) wsum[wid] = x;
    __syncthreads();
    if (wid == 0) {
        int y = wsum[lane];
        #pragma unroll
        for (int off = 1; off < 32; off <<= 1) {
            int t = __shfl_up_sync(0xffffffffu, y, off);
            if (lane >= off) y += t;
        }
        wsum[lane] = y;
    }
    __syncthreads();
    int excl = x - v + (wid ? wsum[wid - 1] : 0);
    if (gid < n) g_rowoff[gid] = excl;
    if (tid == 1023) g_bsum[blockIdx.x] = wsum[31];
}

__global__ void scan_sums_kernel(int nb, int E, int n) {
    __shared__ int s[64];
    int lane = threadIdx.x;
    int v = (lane < nb) ? g_bsum[lane] : 0;
    s[lane] = v;
    __syncthreads();
    #pragma unroll
    for (int off = 1; off < 64; off <<= 1) {
        int t = (lane >= off) ? s[lane - off] : 0;
        __syncthreads();
        s[lane] += t;
        __syncthreads();
    }
    g_boff[lane] = s[lane] - v;
    if (lane == 0) g_rowoff[n] = E;
}

__global__ __launch_bounds__(1024) void scan_add_kernel(int n) {
    int gid = blockIdx.x * 1024 + threadIdx.x;
    if (gid < n) g_rowoff[gid] += g_boff[blockIdx.x];
}

__global__ void scatter_kernel(const int* __restrict__ esrc,
                               const int* __restrict__ edst, int E) {
    int e = blockIdx.x * blockDim.x + threadIdx.x;
    if (e < E) {
        int s = esrc[e];
        int pos = g_rowoff[s] + atomicAdd(&g_cnt[s], 1);
        g_adj[pos] = edst[e];
    }
}

// ------------------------------- GEMM 1 ------------------------------------
// H1[M,512] = A[M,256] @ g_Wcat[256,512] + bias[512]; also emits bf16 H1b.
// 128x128 block tile, 16 k-slice, 256 threads, 8x8 per-thread register tile.
__global__ __launch_bounds__(256) void gemm1_kernel(const float* __restrict__ A,
                                                    const float* __restrict__ bias,
                                                    int M) {
    const int BM = 128, BN = 128, BK = 16;
    __shared__ float As[BK][BM + 4];
    __shared__ float Bs[BK][BN];
    int nblk = F1 / BN;                        // 4
    int bx = blockIdx.x % nblk;
    int by = blockIdx.x / nblk;
    int m0 = by * BM, n0 = bx * BN;
    int tid = threadIdx.x;
    int tr = tid >> 4, tc = tid & 15;          // 16x16 thread grid
    float acc[8][8];
    #pragma unroll
    for (int i = 0; i < 8; i++)
        #pragma unroll
        for (int j = 0; j < 8; j++) acc[i][j] = 0.f;

    for (int k0 = 0; k0 < NFEAT; k0 += BK) {
        // As: 128 rows x 16 k = 512 float4 loads, transposed store
        #pragma unroll
        for (int it = 0; it < 2; it++) {
            int idx = tid + it * 256;          // 0..511
            int row = idx >> 2, kq = idx & 3;
            float4 v = make_float4(0.f, 0.f, 0.f, 0.f);
            int gr = m0 + row;
            if (gr < M)
                v = *(const float4*)(A + (size_t)gr * NFEAT + k0 + kq * 4);
            As[kq * 4 + 0][row] = v.x;
            As[kq * 4 + 1][row] = v.y;
            As[kq * 4 + 2][row] = v.z;
            As[kq * 4 + 3][row] = v.w;
        }
        // Bs: 16 k x 128 cols = 512 float4 loads
        #pragma unroll
        for (int it = 0; it < 2; it++) {
            int idx = tid + it * 256;
            int kr = idx >> 5, cq = idx & 31;
            float4 v = *(const float4*)(g_Wcat + (size_t)(k0 + kr) * F1 + n0 + cq * 4);
            *(float4*)&Bs[kr][cq * 4] = v;
        }
        __syncthreads();
        #pragma unroll
        for (int kk = 0; kk < BK; kk++) {
            float a[8], b[8];
            float4 a0 = *(const float4*)&As[kk][tr * 8];
            float4 a1 = *(const float4*)&As[kk][tr * 8 + 4];
            a[0]=a0.x; a[1]=a0.y; a[2]=a0.z; a[3]=a0.w;
            a[4]=a1.x; a[5]=a1.y; a[6]=a1.z; a[7]=a1.w;
            float4 b0 = *(const float4*)&Bs[kk][tc * 8];
            float4 b1 = *(const float4*)&Bs[kk][tc * 8 + 4];
            b[0]=b0.x; b[1]=b0.y; b[2]=b0.z; b[3]=b0.w;
            b[4]=b1.x; b[5]=b1.y; b[6]=b1.z; b[7]=b1.w;
            #pragma unroll
            for (int i = 0; i < 8; i++)
                #pragma unroll
                for (int j = 0; j < 8; j++) acc[i][j] += a[i] * b[j];
        }
        __syncthreads();
    }
    #pragma unroll
    for (int i = 0; i < 8; i++) {
        int gr = m0 + tr * 8 + i;
        if (gr < M) {
            float vals[8];
            #pragma unroll
            for (int j = 0; j < 8; j++)
                vals[j] = acc[i][j] + bias[n0 + tc * 8 + j];
            size_t base = (size_t)gr * F1 + n0 + tc * 8;
            *(float4*)(g_H1 + base)     = make_float4(vals[0], vals[1], vals[2], vals[3]);
            *(float4*)(g_H1 + base + 4) = make_float4(vals[4], vals[5], vals[6], vals[7]);
            // bf16 copy for aggregation gather
            __nv_bfloat162 p0 = __floats2bfloat162_rn(vals[0], vals[1]);
            __nv_bfloat162 p1 = __floats2bfloat162_rn(vals[2], vals[3]);
            __nv_bfloat162 p2 = __floats2bfloat162_rn(vals[4], vals[5]);
            __nv_bfloat162 p3 = __floats2bfloat162_rn(vals[6], vals[7]);
            uint4 u;
            u.x = *(unsigned*)&p0; u.y = *(unsigned*)&p1;
            u.z = *(unsigned*)&p2; u.w = *(unsigned*)&p3;
            *(uint4*)(g_H1b + base) = u;
        }
    }
}

// ------------------------------- attn1 -------------------------------------
__global__ __launch_bounds__(256) void attn1_kernel(const float* __restrict__ a1) {
    int n = blockIdx.x;
    int w = threadIdx.x >> 5, lane = threadIdx.x & 31;
    const float* hp = g_H1 + (size_t)n * F1 + w * NHID;
    float h0 = hp[lane], h1 = hp[lane + 32];
    const float* av = a1 + w * 2 * NHID;
    float ss = h0 * av[lane] + h1 * av[lane + 32];
    float sd = h0 * av[64 + lane] + h1 * av[96 + lane];
    #pragma unroll
    for (int off = 16; off; off >>= 1) {
        ss += __shfl_down_sync(0xffffffffu, ss, off);
        sd += __shfl_down_sync(0xffffffffu, sd, off);
    }
    if (lane == 0) {
        g_ssrc1[n * NHEAD + w] = ss;
        g_sdst1[n * NHEAD + w] = sd;
    }
}

// ------------------------------- agg1 --------------------------------------
// one block (128 thr) per node; thread t owns features [4t,4t+4) -> head t/16
// gathers bf16 H1b (half the L2 traffic of fp32)
#define CH1 16
__global__ __launch_bounds__(128) void agg1_kernel() {
    int n = blockIdx.x;
    int tid = threadIdx.x;
    __shared__ float sw[CH1 * NHEAD];
    __shared__ int   sdst[CH1];
    __shared__ float srs[NHEAD];
    __shared__ float ssh[NHEAD];
    int head = tid >> 4;
    if (tid < NHEAD) { srs[tid] = 0.f; ssh[tid] = g_ssrc1[n * NHEAD + tid]; }
    int start = g_rowoff[n], end = g_rowoff[n + 1];
    float acc0 = 0.f, acc1 = 0.f, acc2 = 0.f, acc3 = 0.f;
    __syncthreads();

    for (int e0 = start; e0 < end; e0 += CH1) {
        int ne = min(CH1, end - e0);
        if (tid < ne) sdst[tid] = g_adj[e0 + tid];
        __syncthreads();
        if (tid < ne * NHEAD) {
            int i = tid >> 3, h = tid & 7;
            int dst = sdst[i];
            float z = ssh[h] + g_sdst1[dst * NHEAD + h];
            float w = __expf(z > 0.f ? z : ALPHA * z);
            sw[i * NHEAD + h] = w;
            atomicAdd(&srs[h], w);
        }
        __syncthreads();
        for (int i = 0; i < ne; i++) {
            float w = sw[i * NHEAD + head];
            uint2 p = *(const uint2*)(g_H1b + (size_t)sdst[i] * F1 + tid * 4);
            float2 f01 = __bfloat1622float2(*(__nv_bfloat162*)&p.x);
            float2 f23 = __bfloat1622float2(*(__nv_bfloat162*)&p.y);
            acc0 += w * f01.x; acc1 += w * f01.y;
            acc2 += w * f23.x; acc3 += w * f23.y;
        }
        __syncthreads();
    }
    float inv = 1.0f / srs[head];
    acc0 *= inv; acc1 *= inv; acc2 *= inv; acc3 *= inv;
    acc0 = acc0 > 0.f ? acc0 : expm1f(acc0);
    acc1 = acc1 > 0.f ? acc1 : expm1f(acc1);
    acc2 = acc2 > 0.f ? acc2 : expm1f(acc2);
    acc3 = acc3 > 0.f ? acc3 : expm1f(acc3);
    *(float4*)(g_ACC1 + (size_t)n * F1 + tid * 4) = make_float4(acc0, acc1, acc2, acc3);
}

// ------------------------------- GEMM 2 ------------------------------------
__global__ __launch_bounds__(256) void gemm2_kernel(const float* __restrict__ W2,
                                                    const float* __restrict__ b2,
                                                    int M) {
    const int BM = 128, BK = 32;
    __shared__ float As[BK][BM + 1];
    __shared__ float Bs[BK][NCLASS];
    int m0 = blockIdx.x * BM;
    int tid = threadIdx.x;
    int tr = tid >> 3;
    int tc = tid & 7;
    float acc[4][5];
    #pragma unroll
    for (int i = 0; i < 4; i++)
        #pragma unroll
        for (int j = 0; j < 5; j++) acc[i][j] = 0.f;

    for (int k0 = 0; k0 < F1; k0 += BK) {
        #pragma unroll
        for (int it = 0; it < 4; it++) {
            int idx = tid + it * 256;
            int row = idx >> 3, kq = idx & 7;
            float4 v = make_float4(0.f, 0.f, 0.f, 0.f);
            int gr = m0 + row;
            if (gr < M)
                v = *(const float4*)(g_ACC1 + (size_t)gr * F1 + k0 + kq * 4);
            As[kq * 4 + 0][row] = v.x;
            As[kq * 4 + 1][row] = v.y;
            As[kq * 4 + 2][row] = v.z;
            As[kq * 4 + 3][row] = v.w;
        }
        for (int idx = tid; idx < BK * NCLASS; idx += 256) {
            int k = idx / NCLASS, c = idx % NCLASS;
            Bs[k][c] = W2[(size_t)(k0 + k) * NCLASS + c];
        }
        __syncthreads();
        #pragma unroll
        for (int kk = 0; kk < BK; kk++) {
            float b[5];
            #pragma unroll
            for (int j = 0; j < 5; j++) b[j] = Bs[kk][tc * 5 + j];
            #pragma unroll
            for (int i = 0; i < 4; i++) {
                float a = As[kk][tr * 4 + i];
                #pragma unroll
                for (int j = 0; j < 5; j++) acc[i][j] += a * b[j];
            }
        }
        __syncthreads();
    }
    #pragma unroll
    for (int i = 0; i < 4; i++) {
        int gr = m0 + tr * 4 + i;
        if (gr < M) {
            #pragma unroll
            for (int j = 0; j < 5; j++)
                g_H2[(size_t)gr * NCLASS + tc * 5 + j] =
                    acc[i][j] + b2[tc * 5 + j];
        }
    }
}

// ------------------------------- attn2 -------------------------------------
__global__ __launch_bounds__(256) void attn2_kernel(const float* __restrict__ a2, int Nn) {
    int gw = (blockIdx.x * blockDim.x + threadIdx.x) >> 5;
    int lane = threadIdx.x & 31;
    if (gw >= Nn) return;
    const float* hp = g_H2 + (size_t)gw * NCLASS;
    float v0 = hp[lane];
    float ss = v0 * a2[lane];
    float sd = v0 * a2[NCLASS + lane];
    if (lane < NCLASS - 32) {
        float v1 = hp[lane + 32];
        ss += v1 * a2[lane + 32];
        sd += v1 * a2[NCLASS + lane + 32];
    }
    #pragma unroll
    for (int off = 16; off; off >>= 1) {
        ss += __shfl_down_sync(0xffffffffu, ss, off);
        sd += __shfl_down_sync(0xffffffffu, sd, off);
    }
    if (lane == 0) { g_ssrc2[gw] = ss; g_sdst2[gw] = sd; }
}

// --------------------------- agg2 + log_softmax ----------------------------
#define CH2 32
__global__ __launch_bounds__(64) void agg2_kernel(float* __restrict__ out) {
    int n = blockIdx.x;
    int tid = threadIdx.x;
    __shared__ float sw[CH2];
    __shared__ int   sdst[CH2];
    __shared__ float srs;
    __shared__ float red[64];
    if (tid == 0) srs = 0.f;
    int start = g_rowoff[n], end = g_rowoff[n + 1];
    float ssrc = g_ssrc2[n];
    float acc = 0.f;
    __syncthreads();

    for (int e0 = start; e0 < end; e0 += CH2) {
        int ne = min(CH2, end - e0);
        if (tid < ne) {
            int d = g_adj[e0 + tid];
            sdst[tid] = d;
            float z = ssrc + g_sdst2[d];
            float w = __expf(z > 0.f ? z : ALPHA * z);
            sw[tid] = w;
            atomicAdd(&srs, w);
        }
        __syncthreads();
        if (tid < NCLASS) {
            for (int i = 0; i < ne; i++)
                acc += sw[i] * g_H2[(size_t)sdst[i] * NCLASS + tid];
        }
        __syncthreads();
    }
    float v = acc / srs;
    red[tid] = (tid < NCLASS) ? v : -1e30f;
    __syncthreads();
    #pragma unroll
    for (int s = 32; s; s >>= 1) {
        if (tid < s) red[tid] = fmaxf(red[tid], red[tid + s]);
        __syncthreads();
    }
    float mx = red[0];
    __syncthreads();
    red[tid] = (tid < NCLASS) ? __expf(v - mx) : 0.f;
    __syncthreads();
    #pragma unroll
    for (int s = 32; s; s >>= 1) {
        if (tid < s) red[tid] += red[tid + s];
        __syncthreads();
    }
    float lse = logf(red[0]) + mx;
    if (tid < NCLASS) out[(size_t)n * NCLASS + tid] = v - lse;
}

// ------------------------------- launcher ----------------------------------
extern "C" void kernel_launch(void* const* d_in, const int* in_sizes, int n_in,
                              void* d_out, int out_size) {
    const float* x  = (const float*)d_in[0];
    const int*   ed = (const int*)  d_in[1];
    const float* W1 = (const float*)d_in[2];
    const float* b1 = (const float*)d_in[3];
    const float* a1 = (const float*)d_in[4];
    const float* W2 = (const float*)d_in[5];
    const float* b2 = (const float*)d_in[6];
    const float* a2 = (const float*)d_in[7];
    float* out = (float*)d_out;

    int N = in_sizes[0] / NFEAT;
    int E = in_sizes[1] / 2;
    const int* esrc = ed;
    const int* edst = ed + E;
    int NB = (N + 1023) / 1024;

    repack_W1<<<(NHEAD * NFEAT * NHID + 255) / 256, 256>>>(W1);
    zero_counts<<<(N + 255) / 256, 256>>>(N);
    hist_kernel<<<(E + 255) / 256, 256>>>(esrc, E);
    scan_block_kernel<<<NB, 1024>>>(N);
    scan_sums_kernel<<<1, 64>>>(NB, E, N);
    scan_add_kernel<<<NB, 1024>>>(N);
    scatter_kernel<<<(E + 255) / 256, 256>>>(esrc, edst, E);

    gemm1_kernel<<<((N + 127) / 128) * (F1 / 128), 256>>>(x, b1, N);
    attn1_kernel<<<N, 256>>>(a1);
    agg1_kernel<<<N, 128>>>();

    gemm2_kernel<<<(N + 127) / 128, 256>>>(W2, b2, N);
    attn2_kernel<<<(N * 32 + 255) / 256, 256>>>(a2, N);
    agg2_kernel<<<N, 64>>>(out);
}

// round 3
// speedup vs baseline: 1.6418x; 1.4052x over previous
#include <cuda_runtime.h>
#include <cuda_bf16.h>
#include <math.h>
#include <stdint.h>

// ---------------------------------------------------------------------------
// SpGAT R2: bf16 tensor-core GEMM1, factorized edge weights (no per-edge exp),
// sync-free aggregation kernels.
// N=50000, E=1650000, nfeat=256, nhead=8, nhid=64 (F1=512), nclass=40.
// ---------------------------------------------------------------------------

#define NN     50000
#define NFEAT  256
#define NHID   64
#define NHEAD  8
#define F1     512
#define NCLASS 40
#define EMAX   1650000
#define ALPHA  0.2f

// ------------------------- device scratch (static) -------------------------
__device__ __nv_bfloat16 g_Xb  [(size_t)NN * NFEAT];
__device__ __nv_bfloat16 g_WcatT[(size_t)F1 * NFEAT];   // [n][k] bf16
__device__ __nv_bfloat16 g_H1b [(size_t)NN * F1];
__device__ float g_ACC1[(size_t)NN * F1];
__device__ float g_H2  [(size_t)NN * NCLASS];
__device__ float2 g_esrc[NN * NHEAD];   // {exp(ss), exp(0.2 ss)}
__device__ float2 g_edst[NN * NHEAD];   // {exp(sd), exp(0.2 sd)}
__device__ float2 g_e2src[NN];
__device__ float2 g_e2dst[NN];
__device__ int   g_deg[NN];
__device__ int   g_cnt[NN];
__device__ int   g_rowoff[NN + 1];
__device__ int   g_adj[EMAX];
__device__ int   g_bsum[64];
__device__ int   g_boff[64];

// ------------------------------ small kernels ------------------------------
__global__ void cvt_x_kernel(const float* __restrict__ x, int nElem8) {
    int i = blockIdx.x * blockDim.x + threadIdx.x;
    if (i < nElem8) {
        const float4* p = (const float4*)(x) + i * 2;
        float4 v0 = p[0], v1 = p[1];
        __nv_bfloat162 b0 = __floats2bfloat162_rn(v0.x, v0.y);
        __nv_bfloat162 b1 = __floats2bfloat162_rn(v0.z, v0.w);
        __nv_bfloat162 b2 = __floats2bfloat162_rn(v1.x, v1.y);
        __nv_bfloat162 b3 = __floats2bfloat162_rn(v1.z, v1.w);
        uint4 u;
        u.x = *(unsigned*)&b0; u.y = *(unsigned*)&b1;
        u.z = *(unsigned*)&b2; u.w = *(unsigned*)&b3;
        *((uint4*)g_Xb + i) = u;
    }
}

// W1[h][k][j] -> WcatT[(h*64+j)][k]  (bf16)
__global__ void repack_W1T(const float* __restrict__ W1) {
    int idx = blockIdx.x * blockDim.x + threadIdx.x;
    if (idx < NHEAD * NFEAT * NHID) {
        int h = idx / (NFEAT * NHID);
        int r = idx % (NFEAT * NHID);
        int k = r / NHID, j = r % NHID;
        g_WcatT[(size_t)(h * NHID + j) * NFEAT + k] = __float2bfloat16(W1[idx]);
    }
}

__global__ void zero_counts(int n) {
    int i = blockIdx.x * blockDim.x + threadIdx.x;
    if (i < n) { g_deg[i] = 0; g_cnt[i] = 0; }
}

__global__ void hist_kernel(const int* __restrict__ esrc, int E) {
    int e = blockIdx.x * blockDim.x + threadIdx.x;
    if (e < E) atomicAdd(&g_deg[esrc[e]], 1);
}

__global__ __launch_bounds__(1024) void scan_block_kernel(int n) {
    int tid = threadIdx.x;
    int gid = blockIdx.x * 1024 + tid;
    int lane = tid & 31, wid = tid >> 5;
    int v = (gid < n) ? g_deg[gid] : 0;
    int x = v;
    #pragma unroll
    for (int off = 1; off < 32; off <<= 1) {
        int t = __shfl_up_sync(0xffffffffu, x, off);
        if (lane >= off) x += t;
    }
    __shared__ int wsum[32];
    if (lane == 31) wsum[wid] = x;
    __syncthreads();
    if (wid == 0) {
        int y = wsum[lane];
        #pragma unroll
        for (int off = 1; off < 32; off <<= 1) {
            int t = __shfl_up_sync(0xffffffffu, y, off);
            if (lane >= off) y += t;
        }
        wsum[lane] = y;
    }
    __syncthreads();
    int excl = x - v + (wid ? wsum[wid - 1] : 0);
    if (gid < n) g_rowoff[gid] = excl;
    if (tid == 1023) g_bsum[blockIdx.x] = wsum[31];
}

__global__ void scan_sums_kernel(int nb, int E, int n) {
    __shared__ int s[64];
    int lane = threadIdx.x;
    int v = (lane < nb) ? g_bsum[lane] : 0;
    s[lane] = v;
    __syncthreads();
    #pragma unroll
    for (int off = 1; off < 64; off <<= 1) {
        int t = (lane >= off) ? s[lane - off] : 0;
        __syncthreads();
        s[lane] += t;
        __syncthreads();
    }
    g_boff[lane] = s[lane] - v;
    if (lane == 0) g_rowoff[n] = E;
}

__global__ __launch_bounds__(1024) void scan_add_kernel(int n) {
    int gid = blockIdx.x * 1024 + threadIdx.x;
    if (gid < n) g_rowoff[gid] += g_boff[blockIdx.x];
}

__global__ void scatter_kernel(const int* __restrict__ esrc,
                               const int* __restrict__ edst, int E) {
    int e = blockIdx.x * blockDim.x + threadIdx.x;
    if (e < E) {
        int s = esrc[e];
        int pos = g_rowoff[s] + atomicAdd(&g_cnt[s], 1);
        g_adj[pos] = edst[e];
    }
}

// ------------------------------ GEMM1 (mma) --------------------------------
// H1b[M,512](bf16) = Xb[M,256] @ WcatT^T + b1.  BM=128,BN=128,BK=32.
#define LDSM4(R0,R1,R2,R3,addr) \
  asm volatile("ldmatrix.sync.aligned.m8n8.x4.shared.b16 {%0,%1,%2,%3}, [%4];" \
    : "=r"(R0),"=r"(R1),"=r"(R2),"=r"(R3) : "r"(addr))

#define MMA16816(D,A,B0,B1) \
  asm volatile("mma.sync.aligned.m16n8k16.row.col.f32.bf16.bf16.f32 " \
    "{%0,%1,%2,%3}, {%4,%5,%6,%7}, {%8,%9}, {%0,%1,%2,%3};" \
    : "+f"(D[0]),"+f"(D[1]),"+f"(D[2]),"+f"(D[3]) \
    : "r"(A[0]),"r"(A[1]),"r"(A[2]),"r"(A[3]),"r"(B0),"r"(B1))

__global__ __launch_bounds__(256, 2) void gemm1_mma(const float* __restrict__ b1,
                                                    int M) {
    const int PAD = 40;                       // bf16 elems per smem row
    __shared__ __align__(16) __nv_bfloat16 As[128 * PAD];
    __shared__ __align__(16) __nv_bfloat16 Bs[128 * PAD];
    int bx = blockIdx.x & 3;                  // n block (F1/128 = 4)
    int by = blockIdx.x >> 2;
    int m0 = by * 128, n0 = bx * 128;
    int tid = threadIdx.x, lane = tid & 31, wid = tid >> 5;
    int wm = (wid & 3) * 32, wn = (wid >> 2) * 64;

    float acc[2][8][4];
    #pragma unroll
    for (int i = 0; i < 2; i++)
        #pragma unroll
        for (int j = 0; j < 8; j++)
            #pragma unroll
            for (int k = 0; k < 4; k++) acc[i][j][k] = 0.f;

    int lr = lane & 7, lb8 = (lane >> 3) & 1, lhi = lane >> 4;
    uint32_t smA = (uint32_t)__cvta_generic_to_shared(As);
    uint32_t smB = (uint32_t)__cvta_generic_to_shared(Bs);
    // A frag: row = wm + mt*16 + lr + lb8*8 ; col16B-chunk = lhi (ks adds 16 elems)
    uint32_t aAddr = smA + (uint32_t)((wm + lr + lb8 * 8) * PAD + lhi * 8) * 2;
    // B frag: row = wn + ntp*16 + lr + lhi*8 ; col = lb8*8
    uint32_t bAddr = smB + (uint32_t)((wn + lr + lhi * 8) * PAD + lb8 * 8) * 2;

    for (int k0 = 0; k0 < NFEAT; k0 += 32) {
        #pragma unroll
        for (int it = 0; it < 2; it++) {
            int idx = tid + it * 256;         // 0..511
            int row = idx >> 2, q = idx & 3;
            int gr = m0 + row;
            uint4 v = make_uint4(0, 0, 0, 0);
            if (gr < M)
                v = *(const uint4*)(g_Xb + (size_t)gr * NFEAT + k0 + q * 8);
            *(uint4*)(&As[row * PAD + q * 8]) = v;
            uint4 w = *(const uint4*)(g_WcatT + (size_t)(n0 + row) * NFEAT + k0 + q * 8);
            *(uint4*)(&Bs[row * PAD + q * 8]) = w;
        }
        __syncthreads();
        #pragma unroll
        for (int ks = 0; ks < 2; ks++) {
            uint32_t a[2][4], b[4][4];
            #pragma unroll
            for (int mt = 0; mt < 2; mt++)
                LDSM4(a[mt][0], a[mt][1], a[mt][2], a[mt][3],
                      aAddr + mt * 16 * PAD * 2 + ks * 32);
            #pragma unroll
            for (int np = 0; np < 4; np++)
                LDSM4(b[np][0], b[np][1], b[np][2], b[np][3],
                      bAddr + np * 16 * PAD * 2 + ks * 32);
            #pragma unroll
            for (int mt = 0; mt < 2; mt++)
                #pragma unroll
                for (int nt = 0; nt < 8; nt++) {
                    uint32_t b0 = b[nt >> 1][(nt & 1) * 2];
                    uint32_t b1r = b[nt >> 1][(nt & 1) * 2 + 1];
                    MMA16816(acc[mt][nt], a[mt], b0, b1r);
                }
        }
        __syncthreads();
    }

    int gid = lane >> 2, tig = lane & 3;
    #pragma unroll
    for (int mt = 0; mt < 2; mt++) {
        #pragma unroll
        for (int nt = 0; nt < 8; nt++) {
            int r = m0 + wm + mt * 16 + gid;
            int c = n0 + wn + nt * 8 + tig * 2;
            float bb0 = b1[c], bb1 = b1[c + 1];
            if (r < M) {
                __nv_bfloat162 p = __floats2bfloat162_rn(acc[mt][nt][0] + bb0,
                                                         acc[mt][nt][1] + bb1);
                *(unsigned*)(g_H1b + (size_t)r * F1 + c) = *(unsigned*)&p;
            }
            if (r + 8 < M) {
                __nv_bfloat162 p = __floats2bfloat162_rn(acc[mt][nt][2] + bb0,
                                                         acc[mt][nt][3] + bb1);
                *(unsigned*)(g_H1b + (size_t)(r + 8) * F1 + c) = *(unsigned*)&p;
            }
        }
    }
}

// ------------------------------- attn1 -------------------------------------
// block = 1 node, warp w = head w; writes factorized weight tables
__global__ __launch_bounds__(256) void attn1_kernel(const float* __restrict__ a1) {
    int n = blockIdx.x;
    int w = threadIdx.x >> 5, lane = threadIdx.x & 31;
    const __nv_bfloat16* hp = g_H1b + (size_t)n * F1 + w * NHID;
    float h0 = __bfloat162float(hp[lane]);
    float h1 = __bfloat162float(hp[lane + 32]);
    const float* av = a1 + w * 2 * NHID;
    float ss = h0 * av[lane] + h1 * av[lane + 32];
    float sd = h0 * av[64 + lane] + h1 * av[96 + lane];
    #pragma unroll
    for (int off = 16; off; off >>= 1) {
        ss += __shfl_down_sync(0xffffffffu, ss, off);
        sd += __shfl_down_sync(0xffffffffu, sd, off);
    }
    if (lane == 0) {
        g_esrc[n * NHEAD + w] = make_float2(__expf(ss), __expf(ALPHA * ss));
        g_edst[n * NHEAD + w] = make_float2(__expf(sd), __expf(ALPHA * sd));
    }
}

// ------------------------------- agg1 --------------------------------------
// block = 1 node, 128 threads, thread t owns bf16 features [4t,4t+4), head=t/16
// sync-free: weights recomputed per thread from broadcast float2 loads
__global__ __launch_bounds__(128) void agg1_kernel() {
    int n = blockIdx.x;
    int tid = threadIdx.x;
    int head = tid >> 4;
    float2 es = g_esrc[n * NHEAD + head];
    int j = g_rowoff[n], end = g_rowoff[n + 1];
    float a0 = 0.f, a1 = 0.f, a2 = 0.f, a3 = 0.f, sumw = 0.f;
    for (; j < end; j++) {
        int d = __ldg(&g_adj[j]);
        float2 ed = g_edst[d * NHEAD + head];
        float p1 = es.x * ed.x;
        float w = (p1 > 1.f) ? p1 : es.y * ed.y;
        sumw += w;
        uint2 p = *(const uint2*)(g_H1b + (size_t)d * F1 + tid * 4);
        float2 f01 = __bfloat1622float2(*(__nv_bfloat162*)&p.x);
        float2 f23 = __bfloat1622float2(*(__nv_bfloat162*)&p.y);
        a0 += w * f01.x; a1 += w * f01.y;
        a2 += w * f23.x; a3 += w * f23.y;
    }
    float inv = 1.0f / sumw;
    a0 *= inv; a1 *= inv; a2 *= inv; a3 *= inv;
    a0 = a0 > 0.f ? a0 : (__expf(a0) - 1.f);
    a1 = a1 > 0.f ? a1 : (__expf(a1) - 1.f);
    a2 = a2 > 0.f ? a2 : (__expf(a2) - 1.f);
    a3 = a3 > 0.f ? a3 : (__expf(a3) - 1.f);
    *(float4*)(g_ACC1 + (size_t)n * F1 + tid * 4) = make_float4(a0, a1, a2, a3);
}

// ------------------------------- GEMM 2 ------------------------------------
__global__ __launch_bounds__(256) void gemm2_kernel(const float* __restrict__ W2,
                                                    const float* __restrict__ b2,
                                                    int M) {
    const int BM = 128, BK = 32;
    __shared__ float As[BK][BM + 1];
    __shared__ float Bs[BK][NCLASS];
    int m0 = blockIdx.x * BM;
    int tid = threadIdx.x;
    int tr = tid >> 3;
    int tc = tid & 7;
    float acc[4][5];
    #pragma unroll
    for (int i = 0; i < 4; i++)
        #pragma unroll
        for (int j = 0; j < 5; j++) acc[i][j] = 0.f;

    for (int k0 = 0; k0 < F1; k0 += BK) {
        #pragma unroll
        for (int it = 0; it < 4; it++) {
            int idx = tid + it * 256;
            int row = idx >> 3, kq = idx & 7;
            float4 v = make_float4(0.f, 0.f, 0.f, 0.f);
            int gr = m0 + row;
            if (gr < M)
                v = *(const float4*)(g_ACC1 + (size_t)gr * F1 + k0 + kq * 4);
            As[kq * 4 + 0][row] = v.x;
            As[kq * 4 + 1][row] = v.y;
            As[kq * 4 + 2][row] = v.z;
            As[kq * 4 + 3][row] = v.w;
        }
        for (int idx = tid; idx < BK * NCLASS; idx += 256) {
            int k = idx / NCLASS, c = idx % NCLASS;
            Bs[k][c] = W2[(size_t)(k0 + k) * NCLASS + c];
        }
        __syncthreads();
        #pragma unroll
        for (int kk = 0; kk < BK; kk++) {
            float b[5];
            #pragma unroll
            for (int j = 0; j < 5; j++) b[j] = Bs[kk][tc * 5 + j];
            #pragma unroll
            for (int i = 0; i < 4; i++) {
                float a = As[kk][tr * 4 + i];
                #pragma unroll
                for (int j = 0; j < 5; j++) acc[i][j] += a * b[j];
            }
        }
        __syncthreads();
    }
    #pragma unroll
    for (int i = 0; i < 4; i++) {
        int gr = m0 + tr * 4 + i;
        if (gr < M) {
            #pragma unroll
            for (int j = 0; j < 5; j++)
                g_H2[(size_t)gr * NCLASS + tc * 5 + j] =
                    acc[i][j] + b2[tc * 5 + j];
        }
    }
}

// ------------------------------- attn2 -------------------------------------
__global__ __launch_bounds__(256) void attn2_kernel(const float* __restrict__ a2, int Nn) {
    int gw = (blockIdx.x * blockDim.x + threadIdx.x) >> 5;
    int lane = threadIdx.x & 31;
    if (gw >= Nn) return;
    const float* hp = g_H2 + (size_t)gw * NCLASS;
    float v0 = hp[lane];
    float ss = v0 * a2[lane];
    float sd = v0 * a2[NCLASS + lane];
    if (lane < NCLASS - 32) {
        float v1 = hp[lane + 32];
        ss += v1 * a2[lane + 32];
        sd += v1 * a2[NCLASS + lane + 32];
    }
    #pragma unroll
    for (int off = 16; off; off >>= 1) {
        ss += __shfl_down_sync(0xffffffffu, ss, off);
        sd += __shfl_down_sync(0xffffffffu, sd, off);
    }
    if (lane == 0) {
        g_e2src[gw] = make_float2(__expf(ss), __expf(ALPHA * ss));
        g_e2dst[gw] = make_float2(__expf(sd), __expf(ALPHA * sd));
    }
}

// --------------------------- agg2 + log_softmax ----------------------------
__global__ __launch_bounds__(64) void agg2_kernel(float* __restrict__ out) {
    int n = blockIdx.x;
    int tid = threadIdx.x;
    float2 es = g_e2src[n];
    int j = g_rowoff[n], end = g_rowoff[n + 1];
    float acc = 0.f, sumw = 0.f;
    for (; j < end; j++) {
        int d = __ldg(&g_adj[j]);
        float2 ed = g_e2dst[d];
        float p1 = es.x * ed.x;
        float w = (p1 > 1.f) ? p1 : es.y * ed.y;
        sumw += w;
        if (tid < NCLASS) acc += w * g_H2[(size_t)d * NCLASS + tid];
    }
    float v = acc / sumw;

    __shared__ float red[64];
    red[tid] = (tid < NCLASS) ? v : -1e30f;
    __syncthreads();
    #pragma unroll
    for (int s = 32; s; s >>= 1) {
        if (tid < s) red[tid] = fmaxf(red[tid], red[tid + s]);
        __syncthreads();
    }
    float mx = red[0];
    __syncthreads();
    red[tid] = (tid < NCLASS) ? __expf(v - mx) : 0.f;
    __syncthreads();
    #pragma unroll
    for (int s = 32; s; s >>= 1) {
        if (tid < s) red[tid] += red[tid + s];
        __syncthreads();
    }
    float lse = logf(red[0]) + mx;
    if (tid < NCLASS) out[(size_t)n * NCLASS + tid] = v - lse;
}

// ------------------------------- launcher ----------------------------------
extern "C" void kernel_launch(void* const* d_in, const int* in_sizes, int n_in,
                              void* d_out, int out_size) {
    const float* x  = (const float*)d_in[0];
    const int*   ed = (const int*)  d_in[1];
    const float* W1 = (const float*)d_in[2];
    const float* b1 = (const float*)d_in[3];
    const float* a1 = (const float*)d_in[4];
    const float* W2 = (const float*)d_in[5];
    const float* b2 = (const float*)d_in[6];
    const float* a2 = (const float*)d_in[7];
    float* out = (float*)d_out;

    int N = in_sizes[0] / NFEAT;
    int E = in_sizes[1] / 2;
    const int* esrc = ed;
    const int* edst = ed + E;
    int NB = (N + 1023) / 1024;
    int n8 = N * NFEAT / 8;

    cvt_x_kernel<<<(n8 + 255) / 256, 256>>>(x, n8);
    repack_W1T<<<(NHEAD * NFEAT * NHID + 255) / 256, 256>>>(W1);
    zero_counts<<<(N + 255) / 256, 256>>>(N);
    hist_kernel<<<(E + 255) / 256, 256>>>(esrc, E);
    scan_block_kernel<<<NB, 1024>>>(N);
    scan_sums_kernel<<<1, 64>>>(NB, E, N);
    scan_add_kernel<<<NB, 1024>>>(N);
    scatter_kernel<<<(E + 255) / 256, 256>>>(esrc, edst, E);

    gemm1_mma<<<((N + 127) / 128) * (F1 / 128), 256>>>(b1, N);
    attn1_kernel<<<N, 256>>>(a1);
    agg1_kernel<<<N, 128>>>();

    gemm2_kernel<<<(N + 127) / 128, 256>>>(W2, b2, N);
    attn2_kernel<<<(N * 32 + 255) / 256, 256>>>(a2, N);
    agg2_kernel<<<N, 64>>>(out);
}

// round 4
// speedup vs baseline: 2.1010x; 1.2797x over previous
#include <cuda_runtime.h>
#include <cuda_bf16.h>
#include <math.h>
#include <stdint.h>

// ---------------------------------------------------------------------------
// SpGAT R3: smem-staged edge weights in both aggregations (kills redundant
// L2 weight traffic), bf16 ACC1 + tensor-core GEMM2.
// N=50000, E=1650000, nfeat=256, nhead=8, nhid=64 (F1=512), nclass=40.
// ---------------------------------------------------------------------------

#define NN     50000
#define NFEAT  256
#define NHID   64
#define NHEAD  8
#define F1     512
#define NCLASS 40
#define NCPAD  64
#define EMAX   1650000
#define ALPHA  0.2f

// ------------------------- device scratch (static) -------------------------
__device__ __nv_bfloat16 g_Xb   [(size_t)NN * NFEAT];
__device__ __nv_bfloat16 g_WcatT[(size_t)F1 * NFEAT];    // [n][k]
__device__ __nv_bfloat16 g_H1b  [(size_t)NN * F1];
__device__ __nv_bfloat16 g_ACC1b[(size_t)NN * F1];
__device__ __nv_bfloat16 g_W2T  [(size_t)NCPAD * F1];    // [n][k], zero-pad n>=40
__device__ float g_H2  [(size_t)NN * NCLASS];
__device__ float2 g_esrc[NN * NHEAD];
__device__ float2 g_edst[NN * NHEAD];
__device__ float2 g_e2src[NN];
__device__ float2 g_e2dst[NN];
__device__ int   g_deg[NN];
__device__ int   g_cnt[NN];
__device__ int   g_rowoff[NN + 1];
__device__ int   g_adj[EMAX];
__device__ int   g_bsum[64];
__device__ int   g_boff[64];

// ------------------------------ small kernels ------------------------------
__global__ void cvt_x_kernel(const float* __restrict__ x, int nElem8) {
    int i = blockIdx.x * blockDim.x + threadIdx.x;
    if (i < nElem8) {
        const float4* p = (const float4*)(x) + i * 2;
        float4 v0 = p[0], v1 = p[1];
        __nv_bfloat162 b0 = __floats2bfloat162_rn(v0.x, v0.y);
        __nv_bfloat162 b1 = __floats2bfloat162_rn(v0.z, v0.w);
        __nv_bfloat162 b2 = __floats2bfloat162_rn(v1.x, v1.y);
        __nv_bfloat162 b3 = __floats2bfloat162_rn(v1.z, v1.w);
        uint4 u;
        u.x = *(unsigned*)&b0; u.y = *(unsigned*)&b1;
        u.z = *(unsigned*)&b2; u.w = *(unsigned*)&b3;
        *((uint4*)g_Xb + i) = u;
    }
}

__global__ void repack_W1T(const float* __restrict__ W1) {
    int idx = blockIdx.x * blockDim.x + threadIdx.x;
    if (idx < NHEAD * NFEAT * NHID) {
        int h = idx / (NFEAT * NHID);
        int r = idx % (NFEAT * NHID);
        int k = r / NHID, j = r % NHID;
        g_WcatT[(size_t)(h * NHID + j) * NFEAT + k] = __float2bfloat16(W1[idx]);
    }
}

// W2[k][40] -> W2T[n][k] bf16, zero pad n in [40,64)
__global__ void repack_W2T(const float* __restrict__ W2) {
    int idx = blockIdx.x * blockDim.x + threadIdx.x;
    if (idx < NCPAD * F1) {
        int n = idx / F1, k = idx % F1;
        float v = (n < NCLASS) ? W2[(size_t)k * NCLASS + n] : 0.f;
        g_W2T[idx] = __float2bfloat16(v);
    }
}

__global__ void zero_counts(int n) {
    int i = blockIdx.x * blockDim.x + threadIdx.x;
    if (i < n) { g_deg[i] = 0; g_cnt[i] = 0; }
}

__global__ void hist_kernel(const int* __restrict__ esrc, int E) {
    int e = blockIdx.x * blockDim.x + threadIdx.x;
    if (e < E) atomicAdd(&g_deg[esrc[e]], 1);
}

__global__ __launch_bounds__(1024) void scan_block_kernel(int n) {
    int tid = threadIdx.x;
    int gid = blockIdx.x * 1024 + tid;
    int lane = tid & 31, wid = tid >> 5;
    int v = (gid < n) ? g_deg[gid] : 0;
    int x = v;
    #pragma unroll
    for (int off = 1; off < 32; off <<= 1) {
        int t = __shfl_up_sync(0xffffffffu, x, off);
        if (lane >= off) x += t;
    }
    __shared__ int wsum[32];
    if (lane == 31) wsum[wid] = x;
    __syncthreads();
    if (wid == 0) {
        int y = wsum[lane];
        #pragma unroll
        for (int off = 1; off < 32; off <<= 1) {
            int t = __shfl_up_sync(0xffffffffu, y, off);
            if (lane >= off) y += t;
        }
        wsum[lane] = y;
    }
    __syncthreads();
    int excl = x - v + (wid ? wsum[wid - 1] : 0);
    if (gid < n) g_rowoff[gid] = excl;
    if (tid == 1023) g_bsum[blockIdx.x] = wsum[31];
}

__global__ void scan_sums_kernel(int nb, int E, int n) {
    __shared__ int s[64];
    int lane = threadIdx.x;
    int v = (lane < nb) ? g_bsum[lane] : 0;
    s[lane] = v;
    __syncthreads();
    #pragma unroll
    for (int off = 1; off < 64; off <<= 1) {
        int t = (lane >= off) ? s[lane - off] : 0;
        __syncthreads();
        s[lane] += t;
        __syncthreads();
    }
    g_boff[lane] = s[lane] - v;
    if (lane == 0) g_rowoff[n] = E;
}

__global__ __launch_bounds__(1024) void scan_add_kernel(int n) {
    int gid = blockIdx.x * 1024 + threadIdx.x;
    if (gid < n) g_rowoff[gid] += g_boff[blockIdx.x];
}

__global__ void scatter_kernel(const int* __restrict__ esrc,
                               const int* __restrict__ edst, int E) {
    int e = blockIdx.x * blockDim.x + threadIdx.x;
    if (e < E) {
        int s = esrc[e];
        int pos = g_rowoff[s] + atomicAdd(&g_cnt[s], 1);
        g_adj[pos] = edst[e];
    }
}

// ------------------------------ mma helpers --------------------------------
#define LDSM4(R0,R1,R2,R3,addr) \
  asm volatile("ldmatrix.sync.aligned.m8n8.x4.shared.b16 {%0,%1,%2,%3}, [%4];" \
    : "=r"(R0),"=r"(R1),"=r"(R2),"=r"(R3) : "r"(addr))

#define MMA16816(D,A,B0,B1) \
  asm volatile("mma.sync.aligned.m16n8k16.row.col.f32.bf16.bf16.f32 " \
    "{%0,%1,%2,%3}, {%4,%5,%6,%7}, {%8,%9}, {%0,%1,%2,%3};" \
    : "+f"(D[0]),"+f"(D[1]),"+f"(D[2]),"+f"(D[3]) \
    : "r"(A[0]),"r"(A[1]),"r"(A[2]),"r"(A[3]),"r"(B0),"r"(B1))

// ------------------------------ GEMM1 (mma) --------------------------------
__global__ __launch_bounds__(256, 2) void gemm1_mma(const float* __restrict__ b1,
                                                    int M) {
    const int PAD = 40;
    __shared__ __align__(16) __nv_bfloat16 As[128 * PAD];
    __shared__ __align__(16) __nv_bfloat16 Bs[128 * PAD];
    int bx = blockIdx.x & 3;
    int by = blockIdx.x >> 2;
    int m0 = by * 128, n0 = bx * 128;
    int tid = threadIdx.x, lane = tid & 31, wid = tid >> 5;
    int wm = (wid & 3) * 32, wn = (wid >> 2) * 64;

    float acc[2][8][4];
    #pragma unroll
    for (int i = 0; i < 2; i++)
        #pragma unroll
        for (int j = 0; j < 8; j++)
            #pragma unroll
            for (int k = 0; k < 4; k++) acc[i][j][k] = 0.f;

    int lr = lane & 7, lb8 = (lane >> 3) & 1, lhi = lane >> 4;
    uint32_t smA = (uint32_t)__cvta_generic_to_shared(As);
    uint32_t smB = (uint32_t)__cvta_generic_to_shared(Bs);
    uint32_t aAddr = smA + (uint32_t)((wm + lr + lb8 * 8) * PAD + lhi * 8) * 2;
    uint32_t bAddr = smB + (uint32_t)((wn + lr + lhi * 8) * PAD + lb8 * 8) * 2;

    for (int k0 = 0; k0 < NFEAT; k0 += 32) {
        #pragma unroll
        for (int it = 0; it < 2; it++) {
            int idx = tid + it * 256;
            int row = idx >> 2, q = idx & 3;
            int gr = m0 + row;
            uint4 v = make_uint4(0, 0, 0, 0);
            if (gr < M)
                v = *(const uint4*)(g_Xb + (size_t)gr * NFEAT + k0 + q * 8);
            *(uint4*)(&As[row * PAD + q * 8]) = v;
            uint4 w = *(const uint4*)(g_WcatT + (size_t)(n0 + row) * NFEAT + k0 + q * 8);
            *(uint4*)(&Bs[row * PAD + q * 8]) = w;
        }
        __syncthreads();
        #pragma unroll
        for (int ks = 0; ks < 2; ks++) {
            uint32_t a[2][4], b[4][4];
            #pragma unroll
            for (int mt = 0; mt < 2; mt++)
                LDSM4(a[mt][0], a[mt][1], a[mt][2], a[mt][3],
                      aAddr + mt * 16 * PAD * 2 + ks * 32);
            #pragma unroll
            for (int np = 0; np < 4; np++)
                LDSM4(b[np][0], b[np][1], b[np][2], b[np][3],
                      bAddr + np * 16 * PAD * 2 + ks * 32);
            #pragma unroll
            for (int mt = 0; mt < 2; mt++)
                #pragma unroll
                for (int nt = 0; nt < 8; nt++) {
                    uint32_t b0 = b[nt >> 1][(nt & 1) * 2];
                    uint32_t b1r = b[nt >> 1][(nt & 1) * 2 + 1];
                    MMA16816(acc[mt][nt], a[mt], b0, b1r);
                }
        }
        __syncthreads();
    }

    int gid = lane >> 2, tig = lane & 3;
    #pragma unroll
    for (int mt = 0; mt < 2; mt++) {
        #pragma unroll
        for (int nt = 0; nt < 8; nt++) {
            int r = m0 + wm + mt * 16 + gid;
            int c = n0 + wn + nt * 8 + tig * 2;
            float bb0 = b1[c], bb1 = b1[c + 1];
            if (r < M) {
                __nv_bfloat162 p = __floats2bfloat162_rn(acc[mt][nt][0] + bb0,
                                                         acc[mt][nt][1] + bb1);
                *(unsigned*)(g_H1b + (size_t)r * F1 + c) = *(unsigned*)&p;
            }
            if (r + 8 < M) {
                __nv_bfloat162 p = __floats2bfloat162_rn(acc[mt][nt][2] + bb0,
                                                         acc[mt][nt][3] + bb1);
                *(unsigned*)(g_H1b + (size_t)(r + 8) * F1 + c) = *(unsigned*)&p;
            }
        }
    }
}

// ------------------------------- attn1 -------------------------------------
__global__ __launch_bounds__(256) void attn1_kernel(const float* __restrict__ a1) {
    int n = blockIdx.x;
    int w = threadIdx.x >> 5, lane = threadIdx.x & 31;
    const __nv_bfloat16* hp = g_H1b + (size_t)n * F1 + w * NHID;
    float h0 = __bfloat162float(hp[lane]);
    float h1 = __bfloat162float(hp[lane + 32]);
    const float* av = a1 + w * 2 * NHID;
    float ss = h0 * av[lane] + h1 * av[lane + 32];
    float sd = h0 * av[64 + lane] + h1 * av[96 + lane];
    #pragma unroll
    for (int off = 16; off; off >>= 1) {
        ss += __shfl_down_sync(0xffffffffu, ss, off);
        sd += __shfl_down_sync(0xffffffffu, sd, off);
    }
    if (lane == 0) {
        g_esrc[n * NHEAD + w] = make_float2(__expf(ss), __expf(ALPHA * ss));
        g_edst[n * NHEAD + w] = make_float2(__expf(sd), __expf(ALPHA * sd));
    }
}

// ------------------------------- agg1 --------------------------------------
// block = 1 node, 128 thr; smem-staged weights: 8 float2 loads per edge total
#define CH1 32
__global__ __launch_bounds__(128) void agg1_kernel() {
    int n = blockIdx.x;
    int tid = threadIdx.x;
    int head = tid >> 4;
    __shared__ int   sdst[CH1];
    __shared__ float sw[CH1 * NHEAD];
    __shared__ float2 ses[NHEAD];
    if (tid < NHEAD) ses[tid] = g_esrc[n * NHEAD + tid];
    int start = g_rowoff[n], end = g_rowoff[n + 1];
    float a0 = 0.f, a1 = 0.f, a2 = 0.f, a3 = 0.f, sumw = 0.f;
    __syncthreads();

    for (int e0 = start; e0 < end; e0 += CH1) {
        int ne = min(CH1, end - e0);
        if (tid < ne) sdst[tid] = g_adj[e0 + tid];
        __syncthreads();
        #pragma unroll
        for (int it = 0; it < 2; it++) {
            int idx = tid + it * 128;
            if (idx < ne * NHEAD) {
                int i = idx >> 3, h = idx & 7;
                float2 ed = __ldg(&g_edst[sdst[i] * NHEAD + h]);
                float2 es = ses[h];
                float p1 = es.x * ed.x;
                sw[idx] = (p1 > 1.f) ? p1 : es.y * ed.y;
            }
        }
        __syncthreads();
        for (int i = 0; i < ne; i++) {
            float w = sw[i * NHEAD + head];
            sumw += w;
            uint2 p = *(const uint2*)(g_H1b + (size_t)sdst[i] * F1 + tid * 4);
            float2 f01 = __bfloat1622float2(*(__nv_bfloat162*)&p.x);
            float2 f23 = __bfloat1622float2(*(__nv_bfloat162*)&p.y);
            a0 += w * f01.x; a1 += w * f01.y;
            a2 += w * f23.x; a3 += w * f23.y;
        }
        __syncthreads();
    }
    float inv = 1.0f / sumw;
    a0 *= inv; a1 *= inv; a2 *= inv; a3 *= inv;
    a0 = a0 > 0.f ? a0 : (__expf(a0) - 1.f);
    a1 = a1 > 0.f ? a1 : (__expf(a1) - 1.f);
    a2 = a2 > 0.f ? a2 : (__expf(a2) - 1.f);
    a3 = a3 > 0.f ? a3 : (__expf(a3) - 1.f);
    __nv_bfloat162 p0 = __floats2bfloat162_rn(a0, a1);
    __nv_bfloat162 p1 = __floats2bfloat162_rn(a2, a3);
    uint2 u;
    u.x = *(unsigned*)&p0; u.y = *(unsigned*)&p1;
    *(uint2*)(g_ACC1b + (size_t)n * F1 + tid * 4) = u;
}

// ------------------------------ GEMM2 (mma) --------------------------------
// H2[M,40] = ACC1b[M,512] @ W2T^T + b2.  BM=128, BN=64(pad), BK=32.
__global__ __launch_bounds__(256, 2) void gemm2_mma(const float* __restrict__ b2,
                                                    int M) {
    const int PAD = 40;
    __shared__ __align__(16) __nv_bfloat16 As[128 * PAD];
    __shared__ __align__(16) __nv_bfloat16 Bs[64 * PAD];
    int m0 = blockIdx.x * 128;
    int tid = threadIdx.x, lane = tid & 31, wid = tid >> 5;
    int wm = wid * 16;

    float acc[8][4];
    #pragma unroll
    for (int j = 0; j < 8; j++)
        #pragma unroll
        for (int k = 0; k < 4; k++) acc[j][k] = 0.f;

    int lr = lane & 7, lb8 = (lane >> 3) & 1, lhi = lane >> 4;
    uint32_t smA = (uint32_t)__cvta_generic_to_shared(As);
    uint32_t smB = (uint32_t)__cvta_generic_to_shared(Bs);
    uint32_t aAddr = smA + (uint32_t)((wm + lr + lb8 * 8) * PAD + lhi * 8) * 2;
    uint32_t bAddr = smB + (uint32_t)((lr + lhi * 8) * PAD + lb8 * 8) * 2;

    for (int k0 = 0; k0 < F1; k0 += 32) {
        #pragma unroll
        for (int it = 0; it < 2; it++) {
            int idx = tid + it * 256;
            int row = idx >> 2, q = idx & 3;
            int gr = m0 + row;
            uint4 v = make_uint4(0, 0, 0, 0);
            if (gr < M)
                v = *(const uint4*)(g_ACC1b + (size_t)gr * F1 + k0 + q * 8);
            *(uint4*)(&As[row * PAD + q * 8]) = v;
        }
        {
            int row = tid >> 2, q = tid & 3;     // 64 rows x 32 k
            uint4 w = *(const uint4*)(g_W2T + (size_t)row * F1 + k0 + q * 8);
            *(uint4*)(&Bs[row * PAD + q * 8]) = w;
        }
        __syncthreads();
        #pragma unroll
        for (int ks = 0; ks < 2; ks++) {
            uint32_t a[4], b[4][4];
            LDSM4(a[0], a[1], a[2], a[3], aAddr + ks * 32);
            #pragma unroll
            for (int np = 0; np < 4; np++)
                LDSM4(b[np][0], b[np][1], b[np][2], b[np][3],
                      bAddr + np * 16 * PAD * 2 + ks * 32);
            #pragma unroll
            for (int nt = 0; nt < 8; nt++) {
                uint32_t b0 = b[nt >> 1][(nt & 1) * 2];
                uint32_t b1r = b[nt >> 1][(nt & 1) * 2 + 1];
                MMA16816(acc[nt], a, b0, b1r);
            }
        }
        __syncthreads();
    }

    int gid = lane >> 2, tig = lane & 3;
    #pragma unroll
    for (int nt = 0; nt < 5; nt++) {             // cols 0..39 only
        int c = nt * 8 + tig * 2;
        if (c < NCLASS) {
            float bb0 = b2[c], bb1 = b2[c + 1];
            int r = m0 + wm + gid;
            if (r < M) {
                g_H2[(size_t)r * NCLASS + c]     = acc[nt][0] + bb0;
                g_H2[(size_t)r * NCLASS + c + 1] = acc[nt][1] + bb1;
            }
            if (r + 8 < M) {
                g_H2[(size_t)(r + 8) * NCLASS + c]     = acc[nt][2] + bb0;
                g_H2[(size_t)(r + 8) * NCLASS + c + 1] = acc[nt][3] + bb1;
            }
        }
    }
}

// ------------------------------- attn2 -------------------------------------
__global__ __launch_bounds__(256) void attn2_kernel(const float* __restrict__ a2, int Nn) {
    int gw = (blockIdx.x * blockDim.x + threadIdx.x) >> 5;
    int lane = threadIdx.x & 31;
    if (gw >= Nn) return;
    const float* hp = g_H2 + (size_t)gw * NCLASS;
    float v0 = hp[lane];
    float ss = v0 * a2[lane];
    float sd = v0 * a2[NCLASS + lane];
    if (lane < NCLASS - 32) {
        float v1 = hp[lane + 32];
        ss += v1 * a2[lane + 32];
        sd += v1 * a2[NCLASS + lane + 32];
    }
    #pragma unroll
    for (int off = 16; off; off >>= 1) {
        ss += __shfl_down_sync(0xffffffffu, ss, off);
        sd += __shfl_down_sync(0xffffffffu, sd, off);
    }
    if (lane == 0) {
        g_e2src[gw] = make_float2(__expf(ss), __expf(ALPHA * ss));
        g_e2dst[gw] = make_float2(__expf(sd), __expf(ALPHA * sd));
    }
}

// --------------------------- agg2 + log_softmax ----------------------------
#define CH2 64
__global__ __launch_bounds__(64) void agg2_kernel(float* __restrict__ out) {
    int n = blockIdx.x;
    int tid = threadIdx.x;
    __shared__ int   sdst[CH2];
    __shared__ float sw[CH2];
    float2 es = g_e2src[n];
    int start = g_rowoff[n], end = g_rowoff[n + 1];
    float acc = 0.f, sumw = 0.f;

    for (int e0 = start; e0 < end; e0 += CH2) {
        int ne = min(CH2, end - e0);
        if (tid < ne) {
            int d = g_adj[e0 + tid];
            sdst[tid] = d;
            float2 ed = __ldg(&g_e2dst[d]);
            float p1 = es.x * ed.x;
            sw[tid] = (p1 > 1.f) ? p1 : es.y * ed.y;
        }
        __syncthreads();
        for (int i = 0; i < ne; i++) {
            float w = sw[i];
            sumw += w;
            if (tid < NCLASS) acc += w * g_H2[(size_t)sdst[i] * NCLASS + tid];
        }
        __syncthreads();
    }
    float v = acc / sumw;

    __shared__ float red[64];
    red[tid] = (tid < NCLASS) ? v : -1e30f;
    __syncthreads();
    #pragma unroll
    for (int s = 32; s; s >>= 1) {
        if (tid < s) red[tid] = fmaxf(red[tid], red[tid + s]);
        __syncthreads();
    }
    float mx = red[0];
    __syncthreads();
    red[tid] = (tid < NCLASS) ? __expf(v - mx) : 0.f;
    __syncthreads();
    #pragma unroll
    for (int s = 32; s; s >>= 1) {
        if (tid < s) red[tid] += red[tid + s];
        __syncthreads();
    }
    float lse = logf(red[0]) + mx;
    if (tid < NCLASS) out[(size_t)n * NCLASS + tid] = v - lse;
}

// ------------------------------- launcher ----------------------------------
extern "C" void kernel_launch(void* const* d_in, const int* in_sizes, int n_in,
                              void* d_out, int out_size) {
    const float* x  = (const float*)d_in[0];
    const int*   ed = (const int*)  d_in[1];
    const float* W1 = (const float*)d_in[2];
    const float* b1 = (const float*)d_in[3];
    const float* a1 = (const float*)d_in[4];
    const float* W2 = (const float*)d_in[5];
    const float* b2 = (const float*)d_in[6];
    const float* a2 = (const float*)d_in[7];
    float* out = (float*)d_out;

    int N = in_sizes[0] / NFEAT;
    int E = in_sizes[1] / 2;
    const int* esrc = ed;
    const int* edst = ed + E;
    int NB = (N + 1023) / 1024;
    int n8 = N * NFEAT / 8;

    cvt_x_kernel<<<(n8 + 255) / 256, 256>>>(x, n8);
    repack_W1T<<<(NHEAD * NFEAT * NHID + 255) / 256, 256>>>(W1);
    repack_W2T<<<(NCPAD * F1 + 255) / 256, 256>>>(W2);
    zero_counts<<<(N + 255) / 256, 256>>>(N);
    hist_kernel<<<(E + 255) / 256, 256>>>(esrc, E);
    scan_block_kernel<<<NB, 1024>>>(N);
    scan_sums_kernel<<<1, 64>>>(NB, E, N);
    scan_add_kernel<<<NB, 1024>>>(N);
    scatter_kernel<<<(E + 255) / 256, 256>>>(esrc, edst, E);

    gemm1_mma<<<((N + 127) / 128) * (F1 / 128), 256>>>(b1, N);
    attn1_kernel<<<N, 256>>>(a1);
    agg1_kernel<<<N, 128>>>();

    gemm2_mma<<<(N + 127) / 128, 256>>>(b2, N);
    attn2_kernel<<<(N * 32 + 255) / 256, 256>>>(a2, N);
    agg2_kernel<<<N, 64>>>(out);
}

// round 5
// speedup vs baseline: 2.3367x; 1.1122x over previous
#include <cuda_runtime.h>
#include <cuda_bf16.h>
#include <math.h>
#include <stdint.h>

// ---------------------------------------------------------------------------
// SpGAT R4: attention score computation fused into GEMM epilogues (attn1 &
// attn2 kernels deleted), cp.async double-buffered GEMM1, dead-column MMAs
// skipped in GEMM2, CH=64 unrolled aggregation, merged preprocessing.
// ---------------------------------------------------------------------------

#define NN     50000
#define NFEAT  256
#define NHID   64
#define NHEAD  8
#define F1     512
#define NCLASS 40
#define NCPAD  64
#define EMAX   1650000
#define ALPHA  0.2f

// ------------------------- device scratch (static) -------------------------
__device__ __nv_bfloat16 g_Xb   [(size_t)NN * NFEAT];
__device__ __nv_bfloat16 g_WcatT[(size_t)F1 * NFEAT];
__device__ __nv_bfloat16 g_H1b  [(size_t)NN * F1];
__device__ __nv_bfloat16 g_ACC1b[(size_t)NN * F1];
__device__ __nv_bfloat16 g_W2T  [(size_t)NCPAD * F1];
__device__ float g_H2  [(size_t)NN * NCLASS];
__device__ float2 g_esrc[NN * NHEAD];
__device__ float2 g_edst[NN * NHEAD];
__device__ float2 g_e2src[NN];
__device__ float2 g_e2dst[NN];
__device__ int   g_deg[NN];
__device__ int   g_cnt[NN];
__device__ int   g_rowoff[NN + 1];
__device__ int   g_adj[EMAX];
__device__ int   g_bsum[64];
__device__ int   g_boff[64];

// --------------------------- merged preprocessing --------------------------
__global__ void preproc_kernel(const float* __restrict__ x,
                               const float* __restrict__ W1,
                               const float* __restrict__ W2,
                               int n8, int N) {
    int stride = gridDim.x * blockDim.x;
    int g = blockIdx.x * blockDim.x + threadIdx.x;
    for (int i = g; i < n8; i += stride) {
        const float4* p = (const float4*)(x) + i * 2;
        float4 v0 = p[0], v1 = p[1];
        __nv_bfloat162 b0 = __floats2bfloat162_rn(v0.x, v0.y);
        __nv_bfloat162 b1 = __floats2bfloat162_rn(v0.z, v0.w);
        __nv_bfloat162 b2 = __floats2bfloat162_rn(v1.x, v1.y);
        __nv_bfloat162 b3 = __floats2bfloat162_rn(v1.z, v1.w);
        uint4 u;
        u.x = *(unsigned*)&b0; u.y = *(unsigned*)&b1;
        u.z = *(unsigned*)&b2; u.w = *(unsigned*)&b3;
        *((uint4*)g_Xb + i) = u;
    }
    for (int i = g; i < NHEAD * NFEAT * NHID; i += stride) {
        int h = i / (NFEAT * NHID);
        int r = i % (NFEAT * NHID);
        int k = r / NHID, j = r % NHID;
        g_WcatT[(size_t)(h * NHID + j) * NFEAT + k] = __float2bfloat16(W1[i]);
    }
    for (int i = g; i < NCPAD * F1; i += stride) {
        int n = i / F1, k = i % F1;
        float v = (n < NCLASS) ? W2[(size_t)k * NCLASS + n] : 0.f;
        g_W2T[i] = __float2bfloat16(v);
    }
    for (int i = g; i < N; i += stride) { g_deg[i] = 0; g_cnt[i] = 0; }
}

__global__ void hist_kernel(const int* __restrict__ esrc, int E) {
    int e = blockIdx.x * blockDim.x + threadIdx.x;
    if (e < E) atomicAdd(&g_deg[esrc[e]], 1);
}

__global__ __launch_bounds__(1024) void scan_block_kernel(int n) {
    int tid = threadIdx.x;
    int gid = blockIdx.x * 1024 + tid;
    int lane = tid & 31, wid = tid >> 5;
    int v = (gid < n) ? g_deg[gid] : 0;
    int x = v;
    #pragma unroll
    for (int off = 1; off < 32; off <<= 1) {
        int t = __shfl_up_sync(0xffffffffu, x, off);
        if (lane >= off) x += t;
    }
    __shared__ int wsum[32];
    if (lane == 31) wsum[wid] = x;
    __syncthreads();
    if (wid == 0) {
        int y = wsum[lane];
        #pragma unroll
        for (int off = 1; off < 32; off <<= 1) {
            int t = __shfl_up_sync(0xffffffffu, y, off);
            if (lane >= off) y += t;
        }
        wsum[lane] = y;
    }
    __syncthreads();
    int excl = x - v + (wid ? wsum[wid - 1] : 0);
    if (gid < n) g_rowoff[gid] = excl;
    if (tid == 1023) g_bsum[blockIdx.x] = wsum[31];
}

__global__ void scan_sums_kernel(int nb, int E, int n) {
    __shared__ int s[64];
    int lane = threadIdx.x;
    int v = (lane < nb) ? g_bsum[lane] : 0;
    s[lane] = v;
    __syncthreads();
    #pragma unroll
    for (int off = 1; off < 64; off <<= 1) {
        int t = (lane >= off) ? s[lane - off] : 0;
        __syncthreads();
        s[lane] += t;
        __syncthreads();
    }
    g_boff[lane] = s[lane] - v;
    if (lane == 0) g_rowoff[n] = E;
}

__global__ __launch_bounds__(1024) void scan_add_kernel(int n) {
    int gid = blockIdx.x * 1024 + threadIdx.x;
    if (gid < n) g_rowoff[gid] += g_boff[blockIdx.x];
}

__global__ void scatter_kernel(const int* __restrict__ esrc,
                               const int* __restrict__ edst, int E) {
    int e = blockIdx.x * blockDim.x + threadIdx.x;
    if (e < E) {
        int s = esrc[e];
        int pos = g_rowoff[s] + atomicAdd(&g_cnt[s], 1);
        g_adj[pos] = edst[e];
    }
}

// ------------------------------ mma helpers --------------------------------
#define LDSM4(R0,R1,R2,R3,addr) \
  asm volatile("ldmatrix.sync.aligned.m8n8.x4.shared.b16 {%0,%1,%2,%3}, [%4];" \
    : "=r"(R0),"=r"(R1),"=r"(R2),"=r"(R3) : "r"(addr))

#define MMA16816(D,A,B0,B1) \
  asm volatile("mma.sync.aligned.m16n8k16.row.col.f32.bf16.bf16.f32 " \
    "{%0,%1,%2,%3}, {%4,%5,%6,%7}, {%8,%9}, {%0,%1,%2,%3};" \
    : "+f"(D[0]),"+f"(D[1]),"+f"(D[2]),"+f"(D[3]) \
    : "r"(A[0]),"r"(A[1]),"r"(A[2]),"r"(A[3]),"r"(B0),"r"(B1))

#define CP16(dst, src, n) \
  asm volatile("cp.async.cg.shared.global [%0], [%1], 16, %2;" \
    :: "r"(dst), "l"(src), "r"(n))
#define CP_COMMIT asm volatile("cp.async.commit_group;")

// ---------------------- GEMM1 (mma + fused attn1) --------------------------
// H1b[M,512](bf16) = Xb@WcatT^T + b1; also writes per-(node,head) exp tables.
__global__ __launch_bounds__(256, 2) void gemm1_mma(const float* __restrict__ b1,
                                                    const float* __restrict__ a1,
                                                    int M) {
    const int PAD = 40;
    const int BUFE = 128 * PAD;               // elems per buffer
    __shared__ __align__(16) __nv_bfloat16 As[2 * BUFE];
    __shared__ __align__(16) __nv_bfloat16 Bs[2 * BUFE];
    int bx = blockIdx.x & 3;
    int by = blockIdx.x >> 2;
    int m0 = by * 128, n0 = bx * 128;
    int tid = threadIdx.x, lane = tid & 31, wid = tid >> 5;
    int wm = (wid & 3) * 32, wn = (wid >> 2) * 64;

    float acc[2][8][4];
    #pragma unroll
    for (int i = 0; i < 2; i++)
        #pragma unroll
        for (int j = 0; j < 8; j++)
            #pragma unroll
            for (int k = 0; k < 4; k++) acc[i][j][k] = 0.f;

    int lr = lane & 7, lb8 = (lane >> 3) & 1, lhi = lane >> 4;
    uint32_t smA = (uint32_t)__cvta_generic_to_shared(As);
    uint32_t smB = (uint32_t)__cvta_generic_to_shared(Bs);
    uint32_t aBase = (uint32_t)((wm + lr + lb8 * 8) * PAD + lhi * 8) * 2;
    uint32_t bBase = (uint32_t)((wn + lr + lhi * 8) * PAD + lb8 * 8) * 2;

    // staging indices (2 chunks per array per thread)
    int row0 = tid >> 2, q0 = tid & 3;
    int row1 = (tid + 256) >> 2, q1 = (tid + 256) & 3;

    #define STAGE1(buf, k0) {                                                  \
        int gr0 = m0 + row0, gr1 = m0 + row1;                                  \
        CP16(smA + (buf) * BUFE * 2 + (row0 * PAD + q0 * 8) * 2,               \
             g_Xb + (size_t)min(gr0, M - 1) * NFEAT + (k0) + q0 * 8,           \
             gr0 < M ? 16 : 0);                                                \
        CP16(smA + (buf) * BUFE * 2 + (row1 * PAD + q1 * 8) * 2,               \
             g_Xb + (size_t)min(gr1, M - 1) * NFEAT + (k0) + q1 * 8,           \
             gr1 < M ? 16 : 0);                                                \
        CP16(smB + (buf) * BUFE * 2 + (row0 * PAD + q0 * 8) * 2,               \
             g_WcatT + (size_t)(n0 + row0) * NFEAT + (k0) + q0 * 8, 16);       \
        CP16(smB + (buf) * BUFE * 2 + (row1 * PAD + q1 * 8) * 2,               \
             g_WcatT + (size_t)(n0 + row1) * NFEAT + (k0) + q1 * 8, 16);       \
    }

    STAGE1(0, 0); CP_COMMIT;
    for (int kt = 0; kt < 8; kt++) {
        if (kt < 7) { STAGE1((kt + 1) & 1, (kt + 1) * 32); CP_COMMIT; }
        if (kt < 7) asm volatile("cp.async.wait_group 1;");
        else        asm volatile("cp.async.wait_group 0;");
        __syncthreads();
        uint32_t aAddr = smA + (kt & 1) * BUFE * 2 + aBase;
        uint32_t bAddr = smB + (kt & 1) * BUFE * 2 + bBase;
        #pragma unroll
        for (int ks = 0; ks < 2; ks++) {
            uint32_t a[2][4], b[4][4];
            #pragma unroll
            for (int mt = 0; mt < 2; mt++)
                LDSM4(a[mt][0], a[mt][1], a[mt][2], a[mt][3],
                      aAddr + mt * 16 * PAD * 2 + ks * 32);
            #pragma unroll
            for (int np = 0; np < 4; np++)
                LDSM4(b[np][0], b[np][1], b[np][2], b[np][3],
                      bAddr + np * 16 * PAD * 2 + ks * 32);
            #pragma unroll
            for (int mt = 0; mt < 2; mt++)
                #pragma unroll
                for (int nt = 0; nt < 8; nt++) {
                    uint32_t b0 = b[nt >> 1][(nt & 1) * 2];
                    uint32_t b1r = b[nt >> 1][(nt & 1) * 2 + 1];
                    MMA16816(acc[mt][nt], a[mt], b0, b1r);
                }
        }
        __syncthreads();
    }

    // epilogue: store bf16 H1 + fused per-head attention scores
    int gid = lane >> 2, tig = lane & 3;
    int h = (n0 >> 6) + (wid >> 2);            // global head 0..7
    float ss[4] = {0.f, 0.f, 0.f, 0.f};
    float sd[4] = {0.f, 0.f, 0.f, 0.f};
    #pragma unroll
    for (int mt = 0; mt < 2; mt++) {
        #pragma unroll
        for (int nt = 0; nt < 8; nt++) {
            int j = nt * 8 + tig * 2;          // col within head, 0..62
            int c = n0 + wn + j;
            float bb0 = b1[c], bb1 = b1[c + 1];
            float avs0 = a1[h * 128 + j],      avs1 = a1[h * 128 + j + 1];
            float avd0 = a1[h * 128 + 64 + j], avd1 = a1[h * 128 + 64 + j + 1];
            float v0 = acc[mt][nt][0] + bb0, v1 = acc[mt][nt][1] + bb1;
            float v2 = acc[mt][nt][2] + bb0, v3 = acc[mt][nt][3] + bb1;
            ss[mt * 2 + 0] += v0 * avs0 + v1 * avs1;
            sd[mt * 2 + 0] += v0 * avd0 + v1 * avd1;
            ss[mt * 2 + 1] += v2 * avs0 + v3 * avs1;
            sd[mt * 2 + 1] += v2 * avd0 + v3 * avd1;
            int r = m0 + wm + mt * 16 + gid;
            if (r < M) {
                __nv_bfloat162 p = __floats2bfloat162_rn(v0, v1);
                *(unsigned*)(g_H1b + (size_t)r * F1 + c) = *(unsigned*)&p;
            }
            if (r + 8 < M) {
                __nv_bfloat162 p = __floats2bfloat162_rn(v2, v3);
                *(unsigned*)(g_H1b + (size_t)(r + 8) * F1 + c) = *(unsigned*)&p;
            }
        }
    }
    #pragma unroll
    for (int q = 0; q < 4; q++) {
        ss[q] += __shfl_xor_sync(0xffffffffu, ss[q], 1);
        ss[q] += __shfl_xor_sync(0xffffffffu, ss[q], 2);
        sd[q] += __shfl_xor_sync(0xffffffffu, sd[q], 1);
        sd[q] += __shfl_xor_sync(0xffffffffu, sd[q], 2);
    }
    if (tig == 0) {
        #pragma unroll
        for (int q = 0; q < 4; q++) {
            int r = m0 + wm + (q >> 1) * 16 + gid + (q & 1) * 8;
            if (r < M) {
                g_esrc[r * NHEAD + h] = make_float2(__expf(ss[q]), __expf(ALPHA * ss[q]));
                g_edst[r * NHEAD + h] = make_float2(__expf(sd[q]), __expf(ALPHA * sd[q]));
            }
        }
    }
}

// ------------------------------- agg1 --------------------------------------
#define CH1 64
__global__ __launch_bounds__(128) void agg1_kernel() {
    int n = blockIdx.x;
    int tid = threadIdx.x;
    int head = tid >> 4;
    __shared__ int   sdst[CH1];
    __shared__ float sw[CH1 * NHEAD];
    __shared__ float2 ses[NHEAD];
    if (tid < NHEAD) ses[tid] = g_esrc[n * NHEAD + tid];
    int start = g_rowoff[n], end = g_rowoff[n + 1];
    float a0 = 0.f, a1 = 0.f, a2 = 0.f, a3 = 0.f, sumw = 0.f;
    __syncthreads();

    for (int e0 = start; e0 < end; e0 += CH1) {
        int ne = min(CH1, end - e0);
        if (tid < ne) sdst[tid] = g_adj[e0 + tid];
        __syncthreads();
        #pragma unroll
        for (int it = 0; it < 4; it++) {
            int idx = tid + it * 128;
            if (idx < ne * NHEAD) {
                int i = idx >> 3, hh = idx & 7;
                float2 ed = __ldg(&g_edst[sdst[i] * NHEAD + hh]);
                float2 es = ses[hh];
                float p1 = es.x * ed.x;
                sw[idx] = (p1 > 1.f) ? p1 : es.y * ed.y;
            }
        }
        __syncthreads();
        int i = 0;
        for (; i + 2 <= ne; i += 2) {
            float w0 = sw[i * NHEAD + head];
            float w1 = sw[(i + 1) * NHEAD + head];
            uint2 p0 = *(const uint2*)(g_H1b + (size_t)sdst[i] * F1 + tid * 4);
            uint2 p1 = *(const uint2*)(g_H1b + (size_t)sdst[i + 1] * F1 + tid * 4);
            sumw += w0 + w1;
            float2 x01 = __bfloat1622float2(*(__nv_bfloat162*)&p0.x);
            float2 x23 = __bfloat1622float2(*(__nv_bfloat162*)&p0.y);
            float2 y01 = __bfloat1622float2(*(__nv_bfloat162*)&p1.x);
            float2 y23 = __bfloat1622float2(*(__nv_bfloat162*)&p1.y);
            a0 += w0 * x01.x + w1 * y01.x;
            a1 += w0 * x01.y + w1 * y01.y;
            a2 += w0 * x23.x + w1 * y23.x;
            a3 += w0 * x23.y + w1 * y23.y;
        }
        if (i < ne) {
            float w = sw[i * NHEAD + head];
            sumw += w;
            uint2 p = *(const uint2*)(g_H1b + (size_t)sdst[i] * F1 + tid * 4);
            float2 f01 = __bfloat1622float2(*(__nv_bfloat162*)&p.x);
            float2 f23 = __bfloat1622float2(*(__nv_bfloat162*)&p.y);
            a0 += w * f01.x; a1 += w * f01.y;
            a2 += w * f23.x; a3 += w * f23.y;
        }
        __syncthreads();
    }
    float inv = 1.0f / sumw;
    a0 *= inv; a1 *= inv; a2 *= inv; a3 *= inv;
    a0 = a0 > 0.f ? a0 : (__expf(a0) - 1.f);
    a1 = a1 > 0.f ? a1 : (__expf(a1) - 1.f);
    a2 = a2 > 0.f ? a2 : (__expf(a2) - 1.f);
    a3 = a3 > 0.f ? a3 : (__expf(a3) - 1.f);
    __nv_bfloat162 p0 = __floats2bfloat162_rn(a0, a1);
    __nv_bfloat162 p1 = __floats2bfloat162_rn(a2, a3);
    uint2 u;
    u.x = *(unsigned*)&p0; u.y = *(unsigned*)&p1;
    *(uint2*)(g_ACC1b + (size_t)n * F1 + tid * 4) = u;
}

// ---------------------- GEMM2 (mma + fused attn2) --------------------------
__global__ __launch_bounds__(256, 2) void gemm2_mma(const float* __restrict__ b2,
                                                    const float* __restrict__ a2,
                                                    int M) {
    const int PAD = 40;
    __shared__ __align__(16) __nv_bfloat16 As[128 * PAD];
    __shared__ __align__(16) __nv_bfloat16 Bs[64 * PAD];
    int m0 = blockIdx.x * 128;
    int tid = threadIdx.x, lane = tid & 31, wid = tid >> 5;
    int wm = wid * 16;

    float acc[5][4];
    #pragma unroll
    for (int j = 0; j < 5; j++)
        #pragma unroll
        for (int k = 0; k < 4; k++) acc[j][k] = 0.f;

    int lr = lane & 7, lb8 = (lane >> 3) & 1, lhi = lane >> 4;
    uint32_t smA = (uint32_t)__cvta_generic_to_shared(As);
    uint32_t smB = (uint32_t)__cvta_generic_to_shared(Bs);
    uint32_t aAddr = smA + (uint32_t)((wm + lr + lb8 * 8) * PAD + lhi * 8) * 2;
    uint32_t bAddr = smB + (uint32_t)((lr + lhi * 8) * PAD + lb8 * 8) * 2;

    for (int k0 = 0; k0 < F1; k0 += 32) {
        #pragma unroll
        for (int it = 0; it < 2; it++) {
            int idx = tid + it * 256;
            int row = idx >> 2, q = idx & 3;
            int gr = m0 + row;
            uint4 v = make_uint4(0, 0, 0, 0);
            if (gr < M)
                v = *(const uint4*)(g_ACC1b + (size_t)gr * F1 + k0 + q * 8);
            *(uint4*)(&As[row * PAD + q * 8]) = v;
        }
        {
            int row = tid >> 2, q = tid & 3;
            uint4 w = *(const uint4*)(g_W2T + (size_t)row * F1 + k0 + q * 8);
            *(uint4*)(&Bs[row * PAD + q * 8]) = w;
        }
        __syncthreads();
        #pragma unroll
        for (int ks = 0; ks < 2; ks++) {
            uint32_t a[4], b[3][4];
            LDSM4(a[0], a[1], a[2], a[3], aAddr + ks * 32);
            #pragma unroll
            for (int np = 0; np < 3; np++)
                LDSM4(b[np][0], b[np][1], b[np][2], b[np][3],
                      bAddr + np * 16 * PAD * 2 + ks * 32);
            #pragma unroll
            for (int nt = 0; nt < 5; nt++) {
                uint32_t b0 = b[nt >> 1][(nt & 1) * 2];
                uint32_t b1r = b[nt >> 1][(nt & 1) * 2 + 1];
                MMA16816(acc[nt], a, b0, b1r);
            }
        }
        __syncthreads();
    }

    // epilogue: H2 store + fused attn2 scores
    int gid = lane >> 2, tig = lane & 3;
    float ss[2] = {0.f, 0.f}, sd[2] = {0.f, 0.f};
    int r0 = m0 + wm + gid;
    #pragma unroll
    for (int nt = 0; nt < 5; nt++) {
        int c = nt * 8 + tig * 2;              // 0..38
        float bb0 = b2[c], bb1 = b2[c + 1];
        float as0 = a2[c], as1 = a2[c + 1];
        float ad0 = a2[NCLASS + c], ad1 = a2[NCLASS + c + 1];
        float v0 = acc[nt][0] + bb0, v1 = acc[nt][1] + bb1;
        float v2 = acc[nt][2] + bb0, v3 = acc[nt][3] + bb1;
        ss[0] += v0 * as0 + v1 * as1; sd[0] += v0 * ad0 + v1 * ad1;
        ss[1] += v2 * as0 + v3 * as1; sd[1] += v2 * ad0 + v3 * ad1;
        if (r0 < M) {
            g_H2[(size_t)r0 * NCLASS + c]     = v0;
            g_H2[(size_t)r0 * NCLASS + c + 1] = v1;
        }
        if (r0 + 8 < M) {
            g_H2[(size_t)(r0 + 8) * NCLASS + c]     = v2;
            g_H2[(size_t)(r0 + 8) * NCLASS + c + 1] = v3;
        }
    }
    #pragma unroll
    for (int q = 0; q < 2; q++) {
        ss[q] += __shfl_xor_sync(0xffffffffu, ss[q], 1);
        ss[q] += __shfl_xor_sync(0xffffffffu, ss[q], 2);
        sd[q] += __shfl_xor_sync(0xffffffffu, sd[q], 1);
        sd[q] += __shfl_xor_sync(0xffffffffu, sd[q], 2);
    }
    if (tig == 0) {
        #pragma unroll
        for (int q = 0; q < 2; q++) {
            int r = r0 + q * 8;
            if (r < M) {
                g_e2src[r] = make_float2(__expf(ss[q]), __expf(ALPHA * ss[q]));
                g_e2dst[r] = make_float2(__expf(sd[q]), __expf(ALPHA * sd[q]));
            }
        }
    }
}

// --------------------------- agg2 + log_softmax ----------------------------
#define CH2 64
__global__ __launch_bounds__(64) void agg2_kernel(float* __restrict__ out) {
    int n = blockIdx.x;
    int tid = threadIdx.x;
    __shared__ int   sdst[CH2];
    __shared__ float sw[CH2];
    float2 es = g_e2src[n];
    int start = g_rowoff[n], end = g_rowoff[n + 1];
    float acc = 0.f, sumw = 0.f;

    for (int e0 = start; e0 < end; e0 += CH2) {
        int ne = min(CH2, end - e0);
        if (tid < ne) {
            int d = g_adj[e0 + tid];
            sdst[tid] = d;
            float2 ed = __ldg(&g_e2dst[d]);
            float p1 = es.x * ed.x;
            sw[tid] = (p1 > 1.f) ? p1 : es.y * ed.y;
        }
        __syncthreads();
        int i = 0;
        for (; i + 2 <= ne; i += 2) {
            float w0 = sw[i], w1 = sw[i + 1];
            sumw += w0 + w1;
            if (tid < NCLASS) {
                float h0 = g_H2[(size_t)sdst[i] * NCLASS + tid];
                float h1 = g_H2[(size_t)sdst[i + 1] * NCLASS + tid];
                acc += w0 * h0 + w1 * h1;
            }
        }
        if (i < ne) {
            float w = sw[i];
            sumw += w;
            if (tid < NCLASS) acc += w * g_H2[(size_t)sdst[i] * NCLASS + tid];
        }
        __syncthreads();
    }
    float v = acc / sumw;

    __shared__ float red[64];
    red[tid] = (tid < NCLASS) ? v : -1e30f;
    __syncthreads();
    #pragma unroll
    for (int s = 32; s; s >>= 1) {
        if (tid < s) red[tid] = fmaxf(red[tid], red[tid + s]);
        __syncthreads();
    }
    float mx = red[0];
    __syncthreads();
    red[tid] = (tid < NCLASS) ? __expf(v - mx) : 0.f;
    __syncthreads();
    #pragma unroll
    for (int s = 32; s; s >>= 1) {
        if (tid < s) red[tid] += red[tid + s];
        __syncthreads();
    }
    float lse = logf(red[0]) + mx;
    if (tid < NCLASS) out[(size_t)n * NCLASS + tid] = v - lse;
}

// ------------------------------- launcher ----------------------------------
extern "C" void kernel_launch(void* const* d_in, const int* in_sizes, int n_in,
                              void* d_out, int out_size) {
    const float* x  = (const float*)d_in[0];
    const int*   ed = (const int*)  d_in[1];
    const float* W1 = (const float*)d_in[2];
    const float* b1 = (const float*)d_in[3];
    const float* a1 = (const float*)d_in[4];
    const float* W2 = (const float*)d_in[5];
    const float* b2 = (const float*)d_in[6];
    const float* a2 = (const float*)d_in[7];
    float* out = (float*)d_out;

    int N = in_sizes[0] / NFEAT;
    int E = in_sizes[1] / 2;
    const int* esrc = ed;
    const int* edst = ed + E;
    int NB = (N + 1023) / 1024;
    int n8 = N * NFEAT / 8;

    preproc_kernel<<<2048, 256>>>(x, W1, W2, n8, N);
    hist_kernel<<<(E + 255) / 256, 256>>>(esrc, E);
    scan_block_kernel<<<NB, 1024>>>(N);
    scan_sums_kernel<<<1, 64>>>(NB, E, N);
    scan_add_kernel<<<NB, 1024>>>(N);
    scatter_kernel<<<(E + 255) / 256, 256>>>(esrc, edst, E);

    gemm1_mma<<<((N + 127) / 128) * (F1 / 128), 256>>>(b1, a1, N);
    agg1_kernel<<<N, 128>>>();

    gemm2_mma<<<(N + 127) / 128, 256>>>(b2, a2, N);
    agg2_kernel<<<N, 64>>>(out);
}

// round 6
// speedup vs baseline: 2.5223x; 1.0794x over previous
#include <cuda_runtime.h>
#include <cuda_bf16.h>
#include <math.h>
#include <stdint.h>

// ---------------------------------------------------------------------------
// SpGAT R5: forked-stream CSR build overlapped with preproc+GEMM1,
// agg1 with 64-thr/node uint4 gathers, agg2 4-edge unroll.
// ---------------------------------------------------------------------------

#define NN     50000
#define NFEAT  256
#define NHID   64
#define NHEAD  8
#define F1     512
#define NCLASS 40
#define NCPAD  64
#define EMAX   1650000
#define ALPHA  0.2f

// ------------------------- device scratch (static) -------------------------
__device__ __nv_bfloat16 g_Xb   [(size_t)NN * NFEAT];
__device__ __nv_bfloat16 g_WcatT[(size_t)F1 * NFEAT];
__device__ __nv_bfloat16 g_H1b  [(size_t)NN * F1];
__device__ __nv_bfloat16 g_ACC1b[(size_t)NN * F1];
__device__ __nv_bfloat16 g_W2T  [(size_t)NCPAD * F1];
__device__ float g_H2  [(size_t)NN * NCLASS];
__device__ float2 g_esrc[NN * NHEAD];
__device__ float2 g_edst[NN * NHEAD];
__device__ float2 g_e2src[NN];
__device__ float2 g_e2dst[NN];
__device__ int   g_deg[NN];
__device__ int   g_cnt[NN];
__device__ int   g_rowoff[NN + 1];
__device__ int   g_adj[EMAX];
__device__ int   g_bsum[64];
__device__ int   g_boff[64];

// --------------------------- preprocessing (stream 0) ----------------------
__global__ void preproc_kernel(const float* __restrict__ x,
                               const float* __restrict__ W1,
                               const float* __restrict__ W2,
                               int n8) {
    int stride = gridDim.x * blockDim.x;
    int g = blockIdx.x * blockDim.x + threadIdx.x;
    for (int i = g; i < n8; i += stride) {
        const float4* p = (const float4*)(x) + i * 2;
        float4 v0 = p[0], v1 = p[1];
        __nv_bfloat162 b0 = __floats2bfloat162_rn(v0.x, v0.y);
        __nv_bfloat162 b1 = __floats2bfloat162_rn(v0.z, v0.w);
        __nv_bfloat162 b2 = __floats2bfloat162_rn(v1.x, v1.y);
        __nv_bfloat162 b3 = __floats2bfloat162_rn(v1.z, v1.w);
        uint4 u;
        u.x = *(unsigned*)&b0; u.y = *(unsigned*)&b1;
        u.z = *(unsigned*)&b2; u.w = *(unsigned*)&b3;
        *((uint4*)g_Xb + i) = u;
    }
    for (int i = g; i < NHEAD * NFEAT * NHID; i += stride) {
        int h = i / (NFEAT * NHID);
        int r = i % (NFEAT * NHID);
        int k = r / NHID, j = r % NHID;
        g_WcatT[(size_t)(h * NHID + j) * NFEAT + k] = __float2bfloat16(W1[i]);
    }
    for (int i = g; i < NCPAD * F1; i += stride) {
        int n = i / F1, k = i % F1;
        float v = (n < NCLASS) ? W2[(size_t)k * NCLASS + n] : 0.f;
        g_W2T[i] = __float2bfloat16(v);
    }
}

// --------------------------- CSR chain (stream 1) --------------------------
__global__ void zero_counts(int n) {
    int i = blockIdx.x * blockDim.x + threadIdx.x;
    if (i < n) { g_deg[i] = 0; g_cnt[i] = 0; }
}

__global__ void hist_kernel(const int* __restrict__ esrc, int E) {
    int e = blockIdx.x * blockDim.x + threadIdx.x;
    if (e < E) atomicAdd(&g_deg[esrc[e]], 1);
}

__global__ __launch_bounds__(1024) void scan_block_kernel(int n) {
    int tid = threadIdx.x;
    int gid = blockIdx.x * 1024 + tid;
    int lane = tid & 31, wid = tid >> 5;
    int v = (gid < n) ? g_deg[gid] : 0;
    int x = v;
    #pragma unroll
    for (int off = 1; off < 32; off <<= 1) {
        int t = __shfl_up_sync(0xffffffffu, x, off);
        if (lane >= off) x += t;
    }
    __shared__ int wsum[32];
    if (lane == 31) wsum[wid] = x;
    __syncthreads();
    if (wid == 0) {
        int y = wsum[lane];
        #pragma unroll
        for (int off = 1; off < 32; off <<= 1) {
            int t = __shfl_up_sync(0xffffffffu, y, off);
            if (lane >= off) y += t;
        }
        wsum[lane] = y;
    }
    __syncthreads();
    int excl = x - v + (wid ? wsum[wid - 1] : 0);
    if (gid < n) g_rowoff[gid] = excl;
    if (tid == 1023) g_bsum[blockIdx.x] = wsum[31];
}

__global__ void scan_sums_kernel(int nb, int E, int n) {
    __shared__ int s[64];
    int lane = threadIdx.x;
    int v = (lane < nb) ? g_bsum[lane] : 0;
    s[lane] = v;
    __syncthreads();
    #pragma unroll
    for (int off = 1; off < 64; off <<= 1) {
        int t = (lane >= off) ? s[lane - off] : 0;
        __syncthreads();
        s[lane] += t;
        __syncthreads();
    }
    g_boff[lane] = s[lane] - v;
    if (lane == 0) g_rowoff[n] = E;
}

__global__ __launch_bounds__(1024) void scan_add_kernel(int n) {
    int gid = blockIdx.x * 1024 + threadIdx.x;
    if (gid < n) g_rowoff[gid] += g_boff[blockIdx.x];
}

__global__ void scatter_kernel(const int* __restrict__ esrc,
                               const int* __restrict__ edst, int E) {
    int e = blockIdx.x * blockDim.x + threadIdx.x;
    if (e < E) {
        int s = esrc[e];
        int pos = g_rowoff[s] + atomicAdd(&g_cnt[s], 1);
        g_adj[pos] = edst[e];
    }
}

// ------------------------------ mma helpers --------------------------------
#define LDSM4(R0,R1,R2,R3,addr) \
  asm volatile("ldmatrix.sync.aligned.m8n8.x4.shared.b16 {%0,%1,%2,%3}, [%4];" \
    : "=r"(R0),"=r"(R1),"=r"(R2),"=r"(R3) : "r"(addr))

#define MMA16816(D,A,B0,B1) \
  asm volatile("mma.sync.aligned.m16n8k16.row.col.f32.bf16.bf16.f32 " \
    "{%0,%1,%2,%3}, {%4,%5,%6,%7}, {%8,%9}, {%0,%1,%2,%3};" \
    : "+f"(D[0]),"+f"(D[1]),"+f"(D[2]),"+f"(D[3]) \
    : "r"(A[0]),"r"(A[1]),"r"(A[2]),"r"(A[3]),"r"(B0),"r"(B1))

#define CP16(dst, src, n) \
  asm volatile("cp.async.cg.shared.global [%0], [%1], 16, %2;" \
    :: "r"(dst), "l"(src), "r"(n))
#define CP_COMMIT asm volatile("cp.async.commit_group;")

// ---------------------- GEMM1 (mma + fused attn1) --------------------------
__global__ __launch_bounds__(256, 2) void gemm1_mma(const float* __restrict__ b1,
                                                    const float* __restrict__ a1,
                                                    int M) {
    const int PAD = 40;
    const int BUFE = 128 * PAD;
    __shared__ __align__(16) __nv_bfloat16 As[2 * BUFE];
    __shared__ __align__(16) __nv_bfloat16 Bs[2 * BUFE];
    int bx = blockIdx.x & 3;
    int by = blockIdx.x >> 2;
    int m0 = by * 128, n0 = bx * 128;
    int tid = threadIdx.x, lane = tid & 31, wid = tid >> 5;
    int wm = (wid & 3) * 32, wn = (wid >> 2) * 64;

    float acc[2][8][4];
    #pragma unroll
    for (int i = 0; i < 2; i++)
        #pragma unroll
        for (int j = 0; j < 8; j++)
            #pragma unroll
            for (int k = 0; k < 4; k++) acc[i][j][k] = 0.f;

    int lr = lane & 7, lb8 = (lane >> 3) & 1, lhi = lane >> 4;
    uint32_t smA = (uint32_t)__cvta_generic_to_shared(As);
    uint32_t smB = (uint32_t)__cvta_generic_to_shared(Bs);
    uint32_t aBase = (uint32_t)((wm + lr + lb8 * 8) * PAD + lhi * 8) * 2;
    uint32_t bBase = (uint32_t)((wn + lr + lhi * 8) * PAD + lb8 * 8) * 2;

    int row0 = tid >> 2, q0 = tid & 3;
    int row1 = (tid + 256) >> 2, q1 = (tid + 256) & 3;

    #define STAGE1(buf, k0) {                                                  \
        int gr0 = m0 + row0, gr1 = m0 + row1;                                  \
        CP16(smA + (buf) * BUFE * 2 + (row0 * PAD + q0 * 8) * 2,               \
             g_Xb + (size_t)min(gr0, M - 1) * NFEAT + (k0) + q0 * 8,           \
             gr0 < M ? 16 : 0);                                                \
        CP16(smA + (buf) * BUFE * 2 + (row1 * PAD + q1 * 8) * 2,               \
             g_Xb + (size_t)min(gr1, M - 1) * NFEAT + (k0) + q1 * 8,           \
             gr1 < M ? 16 : 0);                                                \
        CP16(smB + (buf) * BUFE * 2 + (row0 * PAD + q0 * 8) * 2,               \
             g_WcatT + (size_t)(n0 + row0) * NFEAT + (k0) + q0 * 8, 16);       \
        CP16(smB + (buf) * BUFE * 2 + (row1 * PAD + q1 * 8) * 2,               \
             g_WcatT + (size_t)(n0 + row1) * NFEAT + (k0) + q1 * 8, 16);       \
    }

    STAGE1(0, 0); CP_COMMIT;
    for (int kt = 0; kt < 8; kt++) {
        if (kt < 7) { STAGE1((kt + 1) & 1, (kt + 1) * 32); CP_COMMIT; }
        if (kt < 7) asm volatile("cp.async.wait_group 1;");
        else        asm volatile("cp.async.wait_group 0;");
        __syncthreads();
        uint32_t aAddr = smA + (kt & 1) * BUFE * 2 + aBase;
        uint32_t bAddr = smB + (kt & 1) * BUFE * 2 + bBase;
        #pragma unroll
        for (int ks = 0; ks < 2; ks++) {
            uint32_t a[2][4], b[4][4];
            #pragma unroll
            for (int mt = 0; mt < 2; mt++)
                LDSM4(a[mt][0], a[mt][1], a[mt][2], a[mt][3],
                      aAddr + mt * 16 * PAD * 2 + ks * 32);
            #pragma unroll
            for (int np = 0; np < 4; np++)
                LDSM4(b[np][0], b[np][1], b[np][2], b[np][3],
                      bAddr + np * 16 * PAD * 2 + ks * 32);
            #pragma unroll
            for (int mt = 0; mt < 2; mt++)
                #pragma unroll
                for (int nt = 0; nt < 8; nt++) {
                    uint32_t b0 = b[nt >> 1][(nt & 1) * 2];
                    uint32_t b1r = b[nt >> 1][(nt & 1) * 2 + 1];
                    MMA16816(acc[mt][nt], a[mt], b0, b1r);
                }
        }
        __syncthreads();
    }

    int gid = lane >> 2, tig = lane & 3;
    int h = (n0 >> 6) + (wid >> 2);
    float ss[4] = {0.f, 0.f, 0.f, 0.f};
    float sd[4] = {0.f, 0.f, 0.f, 0.f};
    #pragma unroll
    for (int mt = 0; mt < 2; mt++) {
        #pragma unroll
        for (int nt = 0; nt < 8; nt++) {
            int j = nt * 8 + tig * 2;
            int c = n0 + wn + j;
            float bb0 = b1[c], bb1 = b1[c + 1];
            float avs0 = a1[h * 128 + j],      avs1 = a1[h * 128 + j + 1];
            float avd0 = a1[h * 128 + 64 + j], avd1 = a1[h * 128 + 64 + j + 1];
            float v0 = acc[mt][nt][0] + bb0, v1 = acc[mt][nt][1] + bb1;
            float v2 = acc[mt][nt][2] + bb0, v3 = acc[mt][nt][3] + bb1;
            ss[mt * 2 + 0] += v0 * avs0 + v1 * avs1;
            sd[mt * 2 + 0] += v0 * avd0 + v1 * avd1;
            ss[mt * 2 + 1] += v2 * avs0 + v3 * avs1;
            sd[mt * 2 + 1] += v2 * avd0 + v3 * avd1;
            int r = m0 + wm + mt * 16 + gid;
            if (r < M) {
                __nv_bfloat162 p = __floats2bfloat162_rn(v0, v1);
                *(unsigned*)(g_H1b + (size_t)r * F1 + c) = *(unsigned*)&p;
            }
            if (r + 8 < M) {
                __nv_bfloat162 p = __floats2bfloat162_rn(v2, v3);
                *(unsigned*)(g_H1b + (size_t)(r + 8) * F1 + c) = *(unsigned*)&p;
            }
        }
    }
    #pragma unroll
    for (int q = 0; q < 4; q++) {
        ss[q] += __shfl_xor_sync(0xffffffffu, ss[q], 1);
        ss[q] += __shfl_xor_sync(0xffffffffu, ss[q], 2);
        sd[q] += __shfl_xor_sync(0xffffffffu, sd[q], 1);
        sd[q] += __shfl_xor_sync(0xffffffffu, sd[q], 2);
    }
    if (tig == 0) {
        #pragma unroll
        for (int q = 0; q < 4; q++) {
            int r = m0 + wm + (q >> 1) * 16 + gid + (q & 1) * 8;
            if (r < M) {
                g_esrc[r * NHEAD + h] = make_float2(__expf(ss[q]), __expf(ALPHA * ss[q]));
                g_edst[r * NHEAD + h] = make_float2(__expf(sd[q]), __expf(ALPHA * sd[q]));
            }
        }
    }
}

// ------------------------------- agg1 --------------------------------------
// 64 threads/node; thread t: head = t/8, features [8t, 8t+8) via uint4 loads
#define CH1 32
__global__ __launch_bounds__(64) void agg1_kernel() {
    int n = blockIdx.x;
    int tid = threadIdx.x;
    int head = tid >> 3;
    __shared__ int   sdst[CH1];
    __shared__ float sw[CH1 * NHEAD];
    __shared__ float2 ses[NHEAD];
    if (tid < NHEAD) ses[tid] = g_esrc[n * NHEAD + tid];
    int start = g_rowoff[n], end = g_rowoff[n + 1];
    float acc[8] = {0.f, 0.f, 0.f, 0.f, 0.f, 0.f, 0.f, 0.f};
    float sumw = 0.f;
    __syncthreads();

    for (int e0 = start; e0 < end; e0 += CH1) {
        int ne = min(CH1, end - e0);
        if (tid < ne) sdst[tid] = g_adj[e0 + tid];
        __syncthreads();
        #pragma unroll
        for (int it = 0; it < 4; it++) {
            int idx = tid + it * 64;
            if (idx < ne * NHEAD) {
                int i = idx >> 3, hh = idx & 7;
                float2 ed = __ldg(&g_edst[sdst[i] * NHEAD + hh]);
                float2 es = ses[hh];
                float p1 = es.x * ed.x;
                sw[idx] = (p1 > 1.f) ? p1 : es.y * ed.y;
            }
        }
        __syncthreads();
        int i = 0;
        for (; i + 2 <= ne; i += 2) {
            float w0 = sw[i * NHEAD + head];
            float w1 = sw[(i + 1) * NHEAD + head];
            uint4 p0 = *(const uint4*)(g_H1b + (size_t)sdst[i] * F1 + tid * 8);
            uint4 p1 = *(const uint4*)(g_H1b + (size_t)sdst[i + 1] * F1 + tid * 8);
            sumw += w0 + w1;
            float2 x0 = __bfloat1622float2(*(__nv_bfloat162*)&p0.x);
            float2 x1 = __bfloat1622float2(*(__nv_bfloat162*)&p0.y);
            float2 x2 = __bfloat1622float2(*(__nv_bfloat162*)&p0.z);
            float2 x3 = __bfloat1622float2(*(__nv_bfloat162*)&p0.w);
            float2 y0 = __bfloat1622float2(*(__nv_bfloat162*)&p1.x);
            float2 y1 = __bfloat1622float2(*(__nv_bfloat162*)&p1.y);
            float2 y2 = __bfloat1622float2(*(__nv_bfloat162*)&p1.z);
            float2 y3 = __bfloat1622float2(*(__nv_bfloat162*)&p1.w);
            acc[0] += w0 * x0.x + w1 * y0.x;
            acc[1] += w0 * x0.y + w1 * y0.y;
            acc[2] += w0 * x1.x + w1 * y1.x;
            acc[3] += w0 * x1.y + w1 * y1.y;
            acc[4] += w0 * x2.x + w1 * y2.x;
            acc[5] += w0 * x2.y + w1 * y2.y;
            acc[6] += w0 * x3.x + w1 * y3.x;
            acc[7] += w0 * x3.y + w1 * y3.y;
        }
        if (i < ne) {
            float w = sw[i * NHEAD + head];
            sumw += w;
            uint4 p = *(const uint4*)(g_H1b + (size_t)sdst[i] * F1 + tid * 8);
            float2 x0 = __bfloat1622float2(*(__nv_bfloat162*)&p.x);
            float2 x1 = __bfloat1622float2(*(__nv_bfloat162*)&p.y);
            float2 x2 = __bfloat1622float2(*(__nv_bfloat162*)&p.z);
            float2 x3 = __bfloat1622float2(*(__nv_bfloat162*)&p.w);
            acc[0] += w * x0.x; acc[1] += w * x0.y;
            acc[2] += w * x1.x; acc[3] += w * x1.y;
            acc[4] += w * x2.x; acc[5] += w * x2.y;
            acc[6] += w * x3.x; acc[7] += w * x3.y;
        }
        __syncthreads();
    }
    float inv = 1.0f / sumw;
    #pragma unroll
    for (int k = 0; k < 8; k++) {
        float v = acc[k] * inv;
        acc[k] = v > 0.f ? v : (__expf(v) - 1.f);
    }
    __nv_bfloat162 q0 = __floats2bfloat162_rn(acc[0], acc[1]);
    __nv_bfloat162 q1 = __floats2bfloat162_rn(acc[2], acc[3]);
    __nv_bfloat162 q2 = __floats2bfloat162_rn(acc[4], acc[5]);
    __nv_bfloat162 q3 = __floats2bfloat162_rn(acc[6], acc[7]);
    uint4 u;
    u.x = *(unsigned*)&q0; u.y = *(unsigned*)&q1;
    u.z = *(unsigned*)&q2; u.w = *(unsigned*)&q3;
    *(uint4*)(g_ACC1b + (size_t)n * F1 + tid * 8) = u;
}

// ---------------------- GEMM2 (mma + fused attn2) --------------------------
__global__ __launch_bounds__(256, 2) void gemm2_mma(const float* __restrict__ b2,
                                                    const float* __restrict__ a2,
                                                    int M) {
    const int PAD = 40;
    __shared__ __align__(16) __nv_bfloat16 As[128 * PAD];
    __shared__ __align__(16) __nv_bfloat16 Bs[64 * PAD];
    int m0 = blockIdx.x * 128;
    int tid = threadIdx.x, lane = tid & 31, wid = tid >> 5;
    int wm = wid * 16;

    float acc[5][4];
    #pragma unroll
    for (int j = 0; j < 5; j++)
        #pragma unroll
        for (int k = 0; k < 4; k++) acc[j][k] = 0.f;

    int lr = lane & 7, lb8 = (lane >> 3) & 1, lhi = lane >> 4;
    uint32_t smA = (uint32_t)__cvta_generic_to_shared(As);
    uint32_t smB = (uint32_t)__cvta_generic_to_shared(Bs);
    uint32_t aAddr = smA + (uint32_t)((wm + lr + lb8 * 8) * PAD + lhi * 8) * 2;
    uint32_t bAddr = smB + (uint32_t)((lr + lhi * 8) * PAD + lb8 * 8) * 2;

    for (int k0 = 0; k0 < F1; k0 += 32) {
        #pragma unroll
        for (int it = 0; it < 2; it++) {
            int idx = tid + it * 256;
            int row = idx >> 2, q = idx & 3;
            int gr = m0 + row;
            uint4 v = make_uint4(0, 0, 0, 0);
            if (gr < M)
                v = *(const uint4*)(g_ACC1b + (size_t)gr * F1 + k0 + q * 8);
            *(uint4*)(&As[row * PAD + q * 8]) = v;
        }
        {
            int row = tid >> 2, q = tid & 3;
            uint4 w = *(const uint4*)(g_W2T + (size_t)row * F1 + k0 + q * 8);
            *(uint4*)(&Bs[row * PAD + q * 8]) = w;
        }
        __syncthreads();
        #pragma unroll
        for (int ks = 0; ks < 2; ks++) {
            uint32_t a[4], b[3][4];
            LDSM4(a[0], a[1], a[2], a[3], aAddr + ks * 32);
            #pragma unroll
            for (int np = 0; np < 3; np++)
                LDSM4(b[np][0], b[np][1], b[np][2], b[np][3],
                      bAddr + np * 16 * PAD * 2 + ks * 32);
            #pragma unroll
            for (int nt = 0; nt < 5; nt++) {
                uint32_t b0 = b[nt >> 1][(nt & 1) * 2];
                uint32_t b1r = b[nt >> 1][(nt & 1) * 2 + 1];
                MMA16816(acc[nt], a, b0, b1r);
            }
        }
        __syncthreads();
    }

    int gid = lane >> 2, tig = lane & 3;
    float ss[2] = {0.f, 0.f}, sd[2] = {0.f, 0.f};
    int r0 = m0 + wm + gid;
    #pragma unroll
    for (int nt = 0; nt < 5; nt++) {
        int c = nt * 8 + tig * 2;
        float bb0 = b2[c], bb1 = b2[c + 1];
        float as0 = a2[c], as1 = a2[c + 1];
        float ad0 = a2[NCLASS + c], ad1 = a2[NCLASS + c + 1];
        float v0 = acc[nt][0] + bb0, v1 = acc[nt][1] + bb1;
        float v2 = acc[nt][2] + bb0, v3 = acc[nt][3] + bb1;
        ss[0] += v0 * as0 + v1 * as1; sd[0] += v0 * ad0 + v1 * ad1;
        ss[1] += v2 * as0 + v3 * as1; sd[1] += v2 * ad0 + v3 * ad1;
        if (r0 < M) {
            g_H2[(size_t)r0 * NCLASS + c]     = v0;
            g_H2[(size_t)r0 * NCLASS + c + 1] = v1;
        }
        if (r0 + 8 < M) {
            g_H2[(size_t)(r0 + 8) * NCLASS + c]     = v2;
            g_H2[(size_t)(r0 + 8) * NCLASS + c + 1] = v3;
        }
    }
    #pragma unroll
    for (int q = 0; q < 2; q++) {
        ss[q] += __shfl_xor_sync(0xffffffffu, ss[q], 1);
        ss[q] += __shfl_xor_sync(0xffffffffu, ss[q], 2);
        sd[q] += __shfl_xor_sync(0xffffffffu, sd[q], 1);
        sd[q] += __shfl_xor_sync(0xffffffffu, sd[q], 2);
    }
    if (tig == 0) {
        #pragma unroll
        for (int q = 0; q < 2; q++) {
            int r = r0 + q * 8;
            if (r < M) {
                g_e2src[r] = make_float2(__expf(ss[q]), __expf(ALPHA * ss[q]));
                g_e2dst[r] = make_float2(__expf(sd[q]), __expf(ALPHA * sd[q]));
            }
        }
    }
}

// --------------------------- agg2 + log_softmax ----------------------------
#define CH2 64
__global__ __launch_bounds__(64) void agg2_kernel(float* __restrict__ out) {
    int n = blockIdx.x;
    int tid = threadIdx.x;
    __shared__ int   sdst[CH2];
    __shared__ float sw[CH2];
    float2 es = g_e2src[n];
    int start = g_rowoff[n], end = g_rowoff[n + 1];
    float acc = 0.f, sumw = 0.f;

    for (int e0 = start; e0 < end; e0 += CH2) {
        int ne = min(CH2, end - e0);
        if (tid < ne) {
            int d = g_adj[e0 + tid];
            sdst[tid] = d;
            float2 ed = __ldg(&g_e2dst[d]);
            float p1 = es.x * ed.x;
            sw[tid] = (p1 > 1.f) ? p1 : es.y * ed.y;
        }
        __syncthreads();
        int i = 0;
        for (; i + 4 <= ne; i += 4) {
            float w0 = sw[i], w1 = sw[i + 1], w2 = sw[i + 2], w3 = sw[i + 3];
            sumw += (w0 + w1) + (w2 + w3);
            if (tid < NCLASS) {
                float h0 = g_H2[(size_t)sdst[i] * NCLASS + tid];
                float h1 = g_H2[(size_t)sdst[i + 1] * NCLASS + tid];
                float h2 = g_H2[(size_t)sdst[i + 2] * NCLASS + tid];
                float h3 = g_H2[(size_t)sdst[i + 3] * NCLASS + tid];
                acc += w0 * h0 + w1 * h1 + w2 * h2 + w3 * h3;
            }
        }
        for (; i < ne; i++) {
            float w = sw[i];
            sumw += w;
            if (tid < NCLASS) acc += w * g_H2[(size_t)sdst[i] * NCLASS + tid];
        }
        __syncthreads();
    }
    float v = acc / sumw;

    __shared__ float red[64];
    red[tid] = (tid < NCLASS) ? v : -1e30f;
    __syncthreads();
    #pragma unroll
    for (int s = 32; s; s >>= 1) {
        if (tid < s) red[tid] = fmaxf(red[tid], red[tid + s]);
        __syncthreads();
    }
    float mx = red[0];
    __syncthreads();
    red[tid] = (tid < NCLASS) ? __expf(v - mx) : 0.f;
    __syncthreads();
    #pragma unroll
    for (int s = 32; s; s >>= 1) {
        if (tid < s) red[tid] += red[tid + s];
        __syncthreads();
    }
    float lse = logf(red[0]) + mx;
    if (tid < NCLASS) out[(size_t)n * NCLASS + tid] = v - lse;
}

// ------------------------------- launcher ----------------------------------
extern "C" void kernel_launch(void* const* d_in, const int* in_sizes, int n_in,
                              void* d_out, int out_size) {
    const float* x  = (const float*)d_in[0];
    const int*   ed = (const int*)  d_in[1];
    const float* W1 = (const float*)d_in[2];
    const float* b1 = (const float*)d_in[3];
    const float* a1 = (const float*)d_in[4];
    const float* W2 = (const float*)d_in[5];
    const float* b2 = (const float*)d_in[6];
    const float* a2 = (const float*)d_in[7];
    float* out = (float*)d_out;

    int N = in_sizes[0] / NFEAT;
    int E = in_sizes[1] / 2;
    const int* esrc = ed;
    const int* edst = ed + E;
    int NB = (N + 1023) / 1024;
    int n8 = N * NFEAT / 8;

    // lazily-created side stream + events (resource caching only; the work
    // performed per call is identical and deterministic)
    static cudaStream_t s1 = nullptr;
    static cudaEvent_t ev0 = nullptr, ev1 = nullptr;
    if (s1 == nullptr) {
        cudaStreamCreateWithFlags(&s1, cudaStreamNonBlocking);
        cudaEventCreateWithFlags(&ev0, cudaEventDisableTiming);
        cudaEventCreateWithFlags(&ev1, cudaEventDisableTiming);
    }

    // fork: CSR chain on s1, dense preproc+GEMM1 on the main stream
    cudaEventRecord(ev0, 0);
    cudaStreamWaitEvent(s1, ev0, 0);

    zero_counts<<<(N + 255) / 256, 256, 0, s1>>>(N);
    hist_kernel<<<(E + 255) / 256, 256, 0, s1>>>(esrc, E);
    scan_block_kernel<<<NB, 1024, 0, s1>>>(N);
    scan_sums_kernel<<<1, 64, 0, s1>>>(NB, E, N);
    scan_add_kernel<<<NB, 1024, 0, s1>>>(N);
    scatter_kernel<<<(E + 255) / 256, 256, 0, s1>>>(esrc, edst, E);
    cudaEventRecord(ev1, s1);

    preproc_kernel<<<2048, 256>>>(x, W1, W2, n8);
    gemm1_mma<<<((N + 127) / 128) * (F1 / 128), 256>>>(b1, a1, N);

    // join: aggregation needs both CSR and H1/scores
    cudaStreamWaitEvent(0, ev1, 0);
    agg1_kernel<<<N, 64>>>();

    gemm2_mma<<<(N + 127) / 128, 256>>>(b2, a2, N);
    agg2_kernel<<<N, 64>>>(out);
}

// round 7
// speedup vs baseline: 2.6302x; 1.0428x over previous
#include <cuda_runtime.h>
#include <cuda_bf16.h>
#include <math.h>
#include <stdint.h>

// ---------------------------------------------------------------------------
// SpGAT R6: scan_sums fused into scan_add, zero via memset nodes, launch
// order arranged so ncu (-s 5) profiles gemm1; agg1 4-edge unrolled.
// ---------------------------------------------------------------------------

#define NN     50000
#define NFEAT  256
#define NHID   64
#define NHEAD  8
#define F1     512
#define NCLASS 40
#define NCPAD  64
#define EMAX   1650000
#define ALPHA  0.2f

// ------------------------- device scratch (static) -------------------------
__device__ __nv_bfloat16 g_Xb   [(size_t)NN * NFEAT];
__device__ __nv_bfloat16 g_WcatT[(size_t)F1 * NFEAT];
__device__ __nv_bfloat16 g_H1b  [(size_t)NN * F1];
__device__ __nv_bfloat16 g_ACC1b[(size_t)NN * F1];
__device__ __nv_bfloat16 g_W2T  [(size_t)NCPAD * F1];
__device__ float g_H2  [(size_t)NN * NCLASS];
__device__ float2 g_esrc[NN * NHEAD];
__device__ float2 g_edst[NN * NHEAD];
__device__ float2 g_e2src[NN];
__device__ float2 g_e2dst[NN];
__device__ int   g_deg[NN];
__device__ int   g_cnt[NN];
__device__ int   g_rowoff[NN + 1];
__device__ int   g_adj[EMAX];
__device__ int   g_bsum[64];

// --------------------------- preprocessing (stream 0) ----------------------
__global__ void preproc_kernel(const float* __restrict__ x,
                               const float* __restrict__ W1,
                               const float* __restrict__ W2,
                               int n8) {
    int stride = gridDim.x * blockDim.x;
    int g = blockIdx.x * blockDim.x + threadIdx.x;
    for (int i = g; i < n8; i += stride) {
        const float4* p = (const float4*)(x) + i * 2;
        float4 v0 = p[0], v1 = p[1];
        __nv_bfloat162 b0 = __floats2bfloat162_rn(v0.x, v0.y);
        __nv_bfloat162 b1 = __floats2bfloat162_rn(v0.z, v0.w);
        __nv_bfloat162 b2 = __floats2bfloat162_rn(v1.x, v1.y);
        __nv_bfloat162 b3 = __floats2bfloat162_rn(v1.z, v1.w);
        uint4 u;
        u.x = *(unsigned*)&b0; u.y = *(unsigned*)&b1;
        u.z = *(unsigned*)&b2; u.w = *(unsigned*)&b3;
        *((uint4*)g_Xb + i) = u;
    }
    for (int i = g; i < NHEAD * NFEAT * NHID; i += stride) {
        int h = i / (NFEAT * NHID);
        int r = i % (NFEAT * NHID);
        int k = r / NHID, j = r % NHID;
        g_WcatT[(size_t)(h * NHID + j) * NFEAT + k] = __float2bfloat16(W1[i]);
    }
    for (int i = g; i < NCPAD * F1; i += stride) {
        int n = i / F1, k = i % F1;
        float v = (n < NCLASS) ? W2[(size_t)k * NCLASS + n] : 0.f;
        g_W2T[i] = __float2bfloat16(v);
    }
}

// --------------------------- CSR chain (stream 1) --------------------------
__global__ void hist_kernel(const int* __restrict__ esrc, int E) {
    int e = blockIdx.x * blockDim.x + threadIdx.x;
    if (e < E) atomicAdd(&g_deg[esrc[e]], 1);
}

__global__ __launch_bounds__(1024) void scan_block_kernel(int n) {
    int tid = threadIdx.x;
    int gid = blockIdx.x * 1024 + tid;
    int lane = tid & 31, wid = tid >> 5;
    int v = (gid < n) ? g_deg[gid] : 0;
    int x = v;
    #pragma unroll
    for (int off = 1; off < 32; off <<= 1) {
        int t = __shfl_up_sync(0xffffffffu, x, off);
        if (lane >= off) x += t;
    }
    __shared__ int wsum[32];
    if (lane == 31) wsum[wid] = x;
    __syncthreads();
    if (wid == 0) {
        int y = wsum[lane];
        #pragma unroll
        for (int off = 1; off < 32; off <<= 1) {
            int t = __shfl_up_sync(0xffffffffu, y, off);
            if (lane >= off) y += t;
        }
        wsum[lane] = y;
    }
    __syncthreads();
    int excl = x - v + (wid ? wsum[wid - 1] : 0);
    if (gid < n) g_rowoff[gid] = excl;
    if (tid == 1023) g_bsum[blockIdx.x] = wsum[31];
}

// fused: every block redundantly scans the <=64 block sums, then adds offset
__global__ __launch_bounds__(1024) void scan_add_kernel(int n, int nb, int E) {
    __shared__ int s[64];
    __shared__ int orig[64];
    int tid = threadIdx.x;
    if (tid < 64) {
        int v = (tid < nb) ? g_bsum[tid] : 0;
        s[tid] = v; orig[tid] = v;
    }
    __syncthreads();
    #pragma unroll
    for (int off = 1; off < 64; off <<= 1) {
        int t = (tid < 64 && tid >= off) ? s[tid - off] : 0;
        __syncthreads();
        if (tid < 64) s[tid] += t;
        __syncthreads();
    }
    int boff = s[blockIdx.x] - orig[blockIdx.x];   // exclusive offset
    int gid = blockIdx.x * 1024 + tid;
    if (gid < n) g_rowoff[gid] += boff;
    if (blockIdx.x == 0 && tid == 0) g_rowoff[n] = E;
}

__global__ void scatter_kernel(const int* __restrict__ esrc,
                               const int* __restrict__ edst, int E) {
    int e = blockIdx.x * blockDim.x + threadIdx.x;
    if (e < E) {
        int s = esrc[e];
        int pos = g_rowoff[s] + atomicAdd(&g_cnt[s], 1);
        g_adj[pos] = edst[e];
    }
}

// ------------------------------ mma helpers --------------------------------
#define LDSM4(R0,R1,R2,R3,addr) \
  asm volatile("ldmatrix.sync.aligned.m8n8.x4.shared.b16 {%0,%1,%2,%3}, [%4];" \
    : "=r"(R0),"=r"(R1),"=r"(R2),"=r"(R3) : "r"(addr))

#define MMA16816(D,A,B0,B1) \
  asm volatile("mma.sync.aligned.m16n8k16.row.col.f32.bf16.bf16.f32 " \
    "{%0,%1,%2,%3}, {%4,%5,%6,%7}, {%8,%9}, {%0,%1,%2,%3};" \
    : "+f"(D[0]),"+f"(D[1]),"+f"(D[2]),"+f"(D[3]) \
    : "r"(A[0]),"r"(A[1]),"r"(A[2]),"r"(A[3]),"r"(B0),"r"(B1))

#define CP16(dst, src, n) \
  asm volatile("cp.async.cg.shared.global [%0], [%1], 16, %2;" \
    :: "r"(dst), "l"(src), "r"(n))
#define CP_COMMIT asm volatile("cp.async.commit_group;")

// ---------------------- GEMM1 (mma + fused attn1) --------------------------
__global__ __launch_bounds__(256, 2) void gemm1_mma(const float* __restrict__ b1,
                                                    const float* __restrict__ a1,
                                                    int M) {
    const int PAD = 40;
    const int BUFE = 128 * PAD;
    __shared__ __align__(16) __nv_bfloat16 As[2 * BUFE];
    __shared__ __align__(16) __nv_bfloat16 Bs[2 * BUFE];
    int bx = blockIdx.x & 3;
    int by = blockIdx.x >> 2;
    int m0 = by * 128, n0 = bx * 128;
    int tid = threadIdx.x, lane = tid & 31, wid = tid >> 5;
    int wm = (wid & 3) * 32, wn = (wid >> 2) * 64;

    float acc[2][8][4];
    #pragma unroll
    for (int i = 0; i < 2; i++)
        #pragma unroll
        for (int j = 0; j < 8; j++)
            #pragma unroll
            for (int k = 0; k < 4; k++) acc[i][j][k] = 0.f;

    int lr = lane & 7, lb8 = (lane >> 3) & 1, lhi = lane >> 4;
    uint32_t smA = (uint32_t)__cvta_generic_to_shared(As);
    uint32_t smB = (uint32_t)__cvta_generic_to_shared(Bs);
    uint32_t aBase = (uint32_t)((wm + lr + lb8 * 8) * PAD + lhi * 8) * 2;
    uint32_t bBase = (uint32_t)((wn + lr + lhi * 8) * PAD + lb8 * 8) * 2;

    int row0 = tid >> 2, q0 = tid & 3;
    int row1 = (tid + 256) >> 2, q1 = (tid + 256) & 3;

    #define STAGE1(buf, k0) {                                                  \
        int gr0 = m0 + row0, gr1 = m0 + row1;                                  \
        CP16(smA + (buf) * BUFE * 2 + (row0 * PAD + q0 * 8) * 2,               \
             g_Xb + (size_t)min(gr0, M - 1) * NFEAT + (k0) + q0 * 8,           \
             gr0 < M ? 16 : 0);                                                \
        CP16(smA + (buf) * BUFE * 2 + (row1 * PAD + q1 * 8) * 2,               \
             g_Xb + (size_t)min(gr1, M - 1) * NFEAT + (k0) + q1 * 8,           \
             gr1 < M ? 16 : 0);                                                \
        CP16(smB + (buf) * BUFE * 2 + (row0 * PAD + q0 * 8) * 2,               \
             g_WcatT + (size_t)(n0 + row0) * NFEAT + (k0) + q0 * 8, 16);       \
        CP16(smB + (buf) * BUFE * 2 + (row1 * PAD + q1 * 8) * 2,               \
             g_WcatT + (size_t)(n0 + row1) * NFEAT + (k0) + q1 * 8, 16);       \
    }

    STAGE1(0, 0); CP_COMMIT;
    for (int kt = 0; kt < 8; kt++) {
        if (kt < 7) { STAGE1((kt + 1) & 1, (kt + 1) * 32); CP_COMMIT; }
        if (kt < 7) asm volatile("cp.async.wait_group 1;");
        else        asm volatile("cp.async.wait_group 0;");
        __syncthreads();
        uint32_t aAddr = smA + (kt & 1) * BUFE * 2 + aBase;
        uint32_t bAddr = smB + (kt & 1) * BUFE * 2 + bBase;
        #pragma unroll
        for (int ks = 0; ks < 2; ks++) {
            uint32_t a[2][4], b[4][4];
            #pragma unroll
            for (int mt = 0; mt < 2; mt++)
                LDSM4(a[mt][0], a[mt][1], a[mt][2], a[mt][3],
                      aAddr + mt * 16 * PAD * 2 + ks * 32);
            #pragma unroll
            for (int np = 0; np < 4; np++)
                LDSM4(b[np][0], b[np][1], b[np][2], b[np][3],
                      bAddr + np * 16 * PAD * 2 + ks * 32);
            #pragma unroll
            for (int mt = 0; mt < 2; mt++)
                #pragma unroll
                for (int nt = 0; nt < 8; nt++) {
                    uint32_t b0 = b[nt >> 1][(nt & 1) * 2];
                    uint32_t b1r = b[nt >> 1][(nt & 1) * 2 + 1];
                    MMA16816(acc[mt][nt], a[mt], b0, b1r);
                }
        }
        __syncthreads();
    }

    int gid = lane >> 2, tig = lane & 3;
    int h = (n0 >> 6) + (wid >> 2);
    float ss[4] = {0.f, 0.f, 0.f, 0.f};
    float sd[4] = {0.f, 0.f, 0.f, 0.f};
    #pragma unroll
    for (int mt = 0; mt < 2; mt++) {
        #pragma unroll
        for (int nt = 0; nt < 8; nt++) {
            int j = nt * 8 + tig * 2;
            int c = n0 + wn + j;
            float bb0 = b1[c], bb1 = b1[c + 1];
            float avs0 = a1[h * 128 + j],      avs1 = a1[h * 128 + j + 1];
            float avd0 = a1[h * 128 + 64 + j], avd1 = a1[h * 128 + 64 + j + 1];
            float v0 = acc[mt][nt][0] + bb0, v1 = acc[mt][nt][1] + bb1;
            float v2 = acc[mt][nt][2] + bb0, v3 = acc[mt][nt][3] + bb1;
            ss[mt * 2 + 0] += v0 * avs0 + v1 * avs1;
            sd[mt * 2 + 0] += v0 * avd0 + v1 * avd1;
            ss[mt * 2 + 1] += v2 * avs0 + v3 * avs1;
            sd[mt * 2 + 1] += v2 * avd0 + v3 * avd1;
            int r = m0 + wm + mt * 16 + gid;
            if (r < M) {
                __nv_bfloat162 p = __floats2bfloat162_rn(v0, v1);
                *(unsigned*)(g_H1b + (size_t)r * F1 + c) = *(unsigned*)&p;
            }
            if (r + 8 < M) {
                __nv_bfloat162 p = __floats2bfloat162_rn(v2, v3);
                *(unsigned*)(g_H1b + (size_t)(r + 8) * F1 + c) = *(unsigned*)&p;
            }
        }
    }
    #pragma unroll
    for (int q = 0; q < 4; q++) {
        ss[q] += __shfl_xor_sync(0xffffffffu, ss[q], 1);
        ss[q] += __shfl_xor_sync(0xffffffffu, ss[q], 2);
        sd[q] += __shfl_xor_sync(0xffffffffu, sd[q], 1);
        sd[q] += __shfl_xor_sync(0xffffffffu, sd[q], 2);
    }
    if (tig == 0) {
        #pragma unroll
        for (int q = 0; q < 4; q++) {
            int r = m0 + wm + (q >> 1) * 16 + gid + (q & 1) * 8;
            if (r < M) {
                g_esrc[r * NHEAD + h] = make_float2(__expf(ss[q]), __expf(ALPHA * ss[q]));
                g_edst[r * NHEAD + h] = make_float2(__expf(sd[q]), __expf(ALPHA * sd[q]));
            }
        }
    }
}

// ------------------------------- agg1 --------------------------------------
// 64 threads/node; thread t: head = t/8, features [8t,8t+8); 4-edge unroll
#define CH1 64
__global__ __launch_bounds__(64) void agg1_kernel() {
    int n = blockIdx.x;
    int tid = threadIdx.x;
    int head = tid >> 3;
    __shared__ int   sdst[CH1];
    __shared__ float sw[CH1 * NHEAD];
    __shared__ float2 ses[NHEAD];
    if (tid < NHEAD) ses[tid] = g_esrc[n * NHEAD + tid];
    int start = g_rowoff[n], end = g_rowoff[n + 1];
    float acc[8] = {0.f, 0.f, 0.f, 0.f, 0.f, 0.f, 0.f, 0.f};
    float sumw = 0.f;
    __syncthreads();

    for (int e0 = start; e0 < end; e0 += CH1) {
        int ne = min(CH1, end - e0);
        if (tid < ne) sdst[tid] = g_adj[e0 + tid];
        __syncthreads();
        #pragma unroll
        for (int it = 0; it < 8; it++) {
            int idx = tid + it * 64;
            if (idx < ne * NHEAD) {
                int i = idx >> 3, hh = idx & 7;
                float2 ed = __ldg(&g_edst[sdst[i] * NHEAD + hh]);
                float2 es = ses[hh];
                float p1 = es.x * ed.x;
                sw[idx] = (p1 > 1.f) ? p1 : es.y * ed.y;
            }
        }
        __syncthreads();
        int i = 0;
        for (; i + 4 <= ne; i += 4) {
            float w0 = sw[(i + 0) * NHEAD + head];
            float w1 = sw[(i + 1) * NHEAD + head];
            float w2 = sw[(i + 2) * NHEAD + head];
            float w3 = sw[(i + 3) * NHEAD + head];
            uint4 p0 = __ldg((const uint4*)(g_H1b + (size_t)sdst[i + 0] * F1 + tid * 8));
            uint4 p1 = __ldg((const uint4*)(g_H1b + (size_t)sdst[i + 1] * F1 + tid * 8));
            uint4 p2 = __ldg((const uint4*)(g_H1b + (size_t)sdst[i + 2] * F1 + tid * 8));
            uint4 p3 = __ldg((const uint4*)(g_H1b + (size_t)sdst[i + 3] * F1 + tid * 8));
            sumw += (w0 + w1) + (w2 + w3);
            float2 f;
            f = __bfloat1622float2(*(__nv_bfloat162*)&p0.x); acc[0] += w0 * f.x; acc[1] += w0 * f.y;
            f = __bfloat1622float2(*(__nv_bfloat162*)&p0.y); acc[2] += w0 * f.x; acc[3] += w0 * f.y;
            f = __bfloat1622float2(*(__nv_bfloat162*)&p0.z); acc[4] += w0 * f.x; acc[5] += w0 * f.y;
            f = __bfloat1622float2(*(__nv_bfloat162*)&p0.w); acc[6] += w0 * f.x; acc[7] += w0 * f.y;
            f = __bfloat1622float2(*(__nv_bfloat162*)&p1.x); acc[0] += w1 * f.x; acc[1] += w1 * f.y;
            f = __bfloat1622float2(*(__nv_bfloat162*)&p1.y); acc[2] += w1 * f.x; acc[3] += w1 * f.y;
            f = __bfloat1622float2(*(__nv_bfloat162*)&p1.z); acc[4] += w1 * f.x; acc[5] += w1 * f.y;
            f = __bfloat1622float2(*(__nv_bfloat162*)&p1.w); acc[6] += w1 * f.x; acc[7] += w1 * f.y;
            f = __bfloat1622float2(*(__nv_bfloat162*)&p2.x); acc[0] += w2 * f.x; acc[1] += w2 * f.y;
            f = __bfloat1622float2(*(__nv_bfloat162*)&p2.y); acc[2] += w2 * f.x; acc[3] += w2 * f.y;
            f = __bfloat1622float2(*(__nv_bfloat162*)&p2.z); acc[4] += w2 * f.x; acc[5] += w2 * f.y;
            f = __bfloat1622float2(*(__nv_bfloat162*)&p2.w); acc[6] += w2 * f.x; acc[7] += w2 * f.y;
            f = __bfloat1622float2(*(__nv_bfloat162*)&p3.x); acc[0] += w3 * f.x; acc[1] += w3 * f.y;
            f = __bfloat1622float2(*(__nv_bfloat162*)&p3.y); acc[2] += w3 * f.x; acc[3] += w3 * f.y;
            f = __bfloat1622float2(*(__nv_bfloat162*)&p3.z); acc[4] += w3 * f.x; acc[5] += w3 * f.y;
            f = __bfloat1622float2(*(__nv_bfloat162*)&p3.w); acc[6] += w3 * f.x; acc[7] += w3 * f.y;
        }
        for (; i < ne; i++) {
            float w = sw[i * NHEAD + head];
            sumw += w;
            uint4 p = __ldg((const uint4*)(g_H1b + (size_t)sdst[i] * F1 + tid * 8));
            float2 f;
            f = __bfloat1622float2(*(__nv_bfloat162*)&p.x); acc[0] += w * f.x; acc[1] += w * f.y;
            f = __bfloat1622float2(*(__nv_bfloat162*)&p.y); acc[2] += w * f.x; acc[3] += w * f.y;
            f = __bfloat1622float2(*(__nv_bfloat162*)&p.z); acc[4] += w * f.x; acc[5] += w * f.y;
            f = __bfloat1622float2(*(__nv_bfloat162*)&p.w); acc[6] += w * f.x; acc[7] += w * f.y;
        }
        __syncthreads();
    }
    float inv = 1.0f / sumw;
    #pragma unroll
    for (int k = 0; k < 8; k++) {
        float v = acc[k] * inv;
        acc[k] = v > 0.f ? v : (__expf(v) - 1.f);
    }
    __nv_bfloat162 q0 = __floats2bfloat162_rn(acc[0], acc[1]);
    __nv_bfloat162 q1 = __floats2bfloat162_rn(acc[2], acc[3]);
    __nv_bfloat162 q2 = __floats2bfloat162_rn(acc[4], acc[5]);
    __nv_bfloat162 q3 = __floats2bfloat162_rn(acc[6], acc[7]);
    uint4 u;
    u.x = *(unsigned*)&q0; u.y = *(unsigned*)&q1;
    u.z = *(unsigned*)&q2; u.w = *(unsigned*)&q3;
    *(uint4*)(g_ACC1b + (size_t)n * F1 + tid * 8) = u;
}

// ---------------------- GEMM2 (mma + fused attn2) --------------------------
__global__ __launch_bounds__(256, 2) void gemm2_mma(const float* __restrict__ b2,
                                                    const float* __restrict__ a2,
                                                    int M) {
    const int PAD = 40;
    __shared__ __align__(16) __nv_bfloat16 As[128 * PAD];
    __shared__ __align__(16) __nv_bfloat16 Bs[64 * PAD];
    int m0 = blockIdx.x * 128;
    int tid = threadIdx.x, lane = tid & 31, wid = tid >> 5;
    int wm = wid * 16;

    float acc[5][4];
    #pragma unroll
    for (int j = 0; j < 5; j++)
        #pragma unroll
        for (int k = 0; k < 4; k++) acc[j][k] = 0.f;

    int lr = lane & 7, lb8 = (lane >> 3) & 1, lhi = lane >> 4;
    uint32_t smA = (uint32_t)__cvta_generic_to_shared(As);
    uint32_t smB = (uint32_t)__cvta_generic_to_shared(Bs);
    uint32_t aAddr = smA + (uint32_t)((wm + lr + lb8 * 8) * PAD + lhi * 8) * 2;
    uint32_t bAddr = smB + (uint32_t)((lr + lhi * 8) * PAD + lb8 * 8) * 2;

    for (int k0 = 0; k0 < F1; k0 += 32) {
        #pragma unroll
        for (int it = 0; it < 2; it++) {
            int idx = tid + it * 256;
            int row = idx >> 2, q = idx & 3;
            int gr = m0 + row;
            uint4 v = make_uint4(0, 0, 0, 0);
            if (gr < M)
                v = *(const uint4*)(g_ACC1b + (size_t)gr * F1 + k0 + q * 8);
            *(uint4*)(&As[row * PAD + q * 8]) = v;
        }
        {
            int row = tid >> 2, q = tid & 3;
            uint4 w = *(const uint4*)(g_W2T + (size_t)row * F1 + k0 + q * 8);
            *(uint4*)(&Bs[row * PAD + q * 8]) = w;
        }
        __syncthreads();
        #pragma unroll
        for (int ks = 0; ks < 2; ks++) {
            uint32_t a[4], b[3][4];
            LDSM4(a[0], a[1], a[2], a[3], aAddr + ks * 32);
            #pragma unroll
            for (int np = 0; np < 3; np++)
                LDSM4(b[np][0], b[np][1], b[np][2], b[np][3],
                      bAddr + np * 16 * PAD * 2 + ks * 32);
            #pragma unroll
            for (int nt = 0; nt < 5; nt++) {
                uint32_t b0 = b[nt >> 1][(nt & 1) * 2];
                uint32_t b1r = b[nt >> 1][(nt & 1) * 2 + 1];
                MMA16816(acc[nt], a, b0, b1r);
            }
        }
        __syncthreads();
    }

    int gid = lane >> 2, tig = lane & 3;
    float ss[2] = {0.f, 0.f}, sd[2] = {0.f, 0.f};
    int r0 = m0 + wm + gid;
    #pragma unroll
    for (int nt = 0; nt < 5; nt++) {
        int c = nt * 8 + tig * 2;
        float bb0 = b2[c], bb1 = b2[c + 1];
        float as0 = a2[c], as1 = a2[c + 1];
        float ad0 = a2[NCLASS + c], ad1 = a2[NCLASS + c + 1];
        float v0 = acc[nt][0] + bb0, v1 = acc[nt][1] + bb1;
        float v2 = acc[nt][2] + bb0, v3 = acc[nt][3] + bb1;
        ss[0] += v0 * as0 + v1 * as1; sd[0] += v0 * ad0 + v1 * ad1;
        ss[1] += v2 * as0 + v3 * as1; sd[1] += v2 * ad0 + v3 * ad1;
        if (r0 < M) {
            g_H2[(size_t)r0 * NCLASS + c]     = v0;
            g_H2[(size_t)r0 * NCLASS + c + 1] = v1;
        }
        if (r0 + 8 < M) {
            g_H2[(size_t)(r0 + 8) * NCLASS + c]     = v2;
            g_H2[(size_t)(r0 + 8) * NCLASS + c + 1] = v3;
        }
    }
    #pragma unroll
    for (int q = 0; q < 2; q++) {
        ss[q] += __shfl_xor_sync(0xffffffffu, ss[q], 1);
        ss[q] += __shfl_xor_sync(0xffffffffu, ss[q], 2);
        sd[q] += __shfl_xor_sync(0xffffffffu, sd[q], 1);
        sd[q] += __shfl_xor_sync(0xffffffffu, sd[q], 2);
    }
    if (tig == 0) {
        #pragma unroll
        for (int q = 0; q < 2; q++) {
            int r = r0 + q * 8;
            if (r < M) {
                g_e2src[r] = make_float2(__expf(ss[q]), __expf(ALPHA * ss[q]));
                g_e2dst[r] = make_float2(__expf(sd[q]), __expf(ALPHA * sd[q]));
            }
        }
    }
}

// --------------------------- agg2 + log_softmax ----------------------------
#define CH2 64
__global__ __launch_bounds__(64) void agg2_kernel(float* __restrict__ out) {
    int n = blockIdx.x;
    int tid = threadIdx.x;
    __shared__ int   sdst[CH2];
    __shared__ float sw[CH2];
    float2 es = g_e2src[n];
    int start = g_rowoff[n], end = g_rowoff[n + 1];
    float acc = 0.f, sumw = 0.f;

    for (int e0 = start; e0 < end; e0 += CH2) {
        int ne = min(CH2, end - e0);
        if (tid < ne) {
            int d = g_adj[e0 + tid];
            sdst[tid] = d;
            float2 ed = __ldg(&g_e2dst[d]);
            float p1 = es.x * ed.x;
            sw[tid] = (p1 > 1.f) ? p1 : es.y * ed.y;
        }
        __syncthreads();
        int i = 0;
        for (; i + 4 <= ne; i += 4) {
            float w0 = sw[i], w1 = sw[i + 1], w2 = sw[i + 2], w3 = sw[i + 3];
            sumw += (w0 + w1) + (w2 + w3);
            if (tid < NCLASS) {
                float h0 = g_H2[(size_t)sdst[i] * NCLASS + tid];
                float h1 = g_H2[(size_t)sdst[i + 1] * NCLASS + tid];
                float h2 = g_H2[(size_t)sdst[i + 2] * NCLASS + tid];
                float h3 = g_H2[(size_t)sdst[i + 3] * NCLASS + tid];
                acc += w0 * h0 + w1 * h1 + w2 * h2 + w3 * h3;
            }
        }
        for (; i < ne; i++) {
            float w = sw[i];
            sumw += w;
            if (tid < NCLASS) acc += w * g_H2[(size_t)sdst[i] * NCLASS + tid];
        }
        __syncthreads();
    }
    float v = acc / sumw;

    __shared__ float red[64];
    red[tid] = (tid < NCLASS) ? v : -1e30f;
    __syncthreads();
    #pragma unroll
    for (int s = 32; s; s >>= 1) {
        if (tid < s) red[tid] = fmaxf(red[tid], red[tid + s]);
        __syncthreads();
    }
    float mx = red[0];
    __syncthreads();
    red[tid] = (tid < NCLASS) ? __expf(v - mx) : 0.f;
    __syncthreads();
    #pragma unroll
    for (int s = 32; s; s >>= 1) {
        if (tid < s) red[tid] += red[tid + s];
        __syncthreads();
    }
    float lse = logf(red[0]) + mx;
    if (tid < NCLASS) out[(size_t)n * NCLASS + tid] = v - lse;
}

// ------------------------------- launcher ----------------------------------
extern "C" void kernel_launch(void* const* d_in, const int* in_sizes, int n_in,
                              void* d_out, int out_size) {
    const float* x  = (const float*)d_in[0];
    const int*   ed = (const int*)  d_in[1];
    const float* W1 = (const float*)d_in[2];
    const float* b1 = (const float*)d_in[3];
    const float* a1 = (const float*)d_in[4];
    const float* W2 = (const float*)d_in[5];
    const float* b2 = (const float*)d_in[6];
    const float* a2 = (const float*)d_in[7];
    float* out = (float*)d_out;

    int N = in_sizes[0] / NFEAT;
    int E = in_sizes[1] / 2;
    const int* esrc = ed;
    const int* edst = ed + E;
    int NB = (N + 1023) / 1024;
    int n8 = N * NFEAT / 8;

    static cudaStream_t s1 = nullptr;
    static cudaEvent_t ev0 = nullptr, ev1 = nullptr;
    static void *p_deg = nullptr, *p_cnt = nullptr;
    if (s1 == nullptr) {
        cudaStreamCreateWithFlags(&s1, cudaStreamNonBlocking);
        cudaEventCreateWithFlags(&ev0, cudaEventDisableTiming);
        cudaEventCreateWithFlags(&ev1, cudaEventDisableTiming);
        cudaGetSymbolAddress(&p_deg, g_deg);
        cudaGetSymbolAddress(&p_cnt, g_cnt);
    }

    // fork: CSR chain on s1, dense preproc+GEMM1 on the main stream
    cudaEventRecord(ev0, 0);
    cudaStreamWaitEvent(s1, ev0, 0);

    // submission order chosen so kernel-launch #6 (ncu -s 5) is gemm1_mma
    preproc_kernel<<<2048, 256>>>(x, W1, W2, n8);                       // 1
    cudaMemsetAsync(p_deg, 0, N * sizeof(int), s1);
    cudaMemsetAsync(p_cnt, 0, N * sizeof(int), s1);
    hist_kernel<<<(E + 255) / 256, 256, 0, s1>>>(esrc, E);              // 2
    scan_block_kernel<<<NB, 1024, 0, s1>>>(N);                          // 3
    scan_add_kernel<<<NB, 1024, 0, s1>>>(N, NB, E);                     // 4
    scatter_kernel<<<(E + 255) / 256, 256, 0, s1>>>(esrc, edst, E);     // 5
    cudaEventRecord(ev1, s1);

    gemm1_mma<<<((N + 127) / 128) * (F1 / 128), 256>>>(b1, a1, N);      // 6 ← profiled

    cudaStreamWaitEvent(0, ev1, 0);
    agg1_kernel<<<N, 64>>>();                                           // 7

    gemm2_mma<<<(N + 127) / 128, 256>>>(b2, a2, N);                     // 8
    agg2_kernel<<<N, 64>>>(out);                                        // 9
}